// round 13
// baseline (speedup 1.0000x reference)
#include <cuda_runtime.h>
#include <cuda_bf16.h>
#include <math.h>
#include <stdint.h>

#define BB 4
#define SS 2048
#define HH 512
#define NH 8
#define DKK 64

// ---------------- bf16 split + mma.sync helpers (baseline PTX) ---------------
__device__ __forceinline__ uint32_t packbf(float lo, float hi) {
    uint32_t r; asm("cvt.rn.bf16x2.f32 %0, %2, %1;" : "=r"(r) : "f"(lo), "f"(hi)); return r;
}
__device__ __forceinline__ void pack_hl(float e0, float e1, uint32_t& h, uint32_t& l) {
    h = packbf(e0, e1);
    float a = __uint_as_float(h << 16);
    float b = __uint_as_float(h & 0xFFFF0000u);
    l = packbf(e0 - a, e1 - b);
}
__device__ __forceinline__ void ldsm4(uint32_t& r0, uint32_t& r1, uint32_t& r2, uint32_t& r3,
                                      uint32_t a) {
    asm volatile("ldmatrix.sync.aligned.m8n8.x4.shared.b16 {%0,%1,%2,%3}, [%4];"
                 : "=r"(r0), "=r"(r1), "=r"(r2), "=r"(r3) : "r"(a));
}
__device__ __forceinline__ void ldsm2(uint32_t& r0, uint32_t& r1, uint32_t a) {
    asm volatile("ldmatrix.sync.aligned.m8n8.x2.shared.b16 {%0,%1}, [%2];"
                 : "=r"(r0), "=r"(r1) : "r"(a));
}
__device__ __forceinline__ void ldsm2t(uint32_t& r0, uint32_t& r1, uint32_t a) {
    asm volatile("ldmatrix.sync.aligned.m8n8.x2.trans.shared.b16 {%0,%1}, [%2];"
                 : "=r"(r0), "=r"(r1) : "r"(a));
}
__device__ __forceinline__ void ldsm4t(uint32_t& r0, uint32_t& r1, uint32_t& r2, uint32_t& r3,
                                       uint32_t a) {
    asm volatile("ldmatrix.sync.aligned.m8n8.x4.trans.shared.b16 {%0,%1,%2,%3}, [%4];"
                 : "=r"(r0), "=r"(r1), "=r"(r2), "=r"(r3) : "r"(a));
}
__device__ __forceinline__ void mma_bf16(float* c, uint32_t a0, uint32_t a1,
                                         uint32_t a2, uint32_t a3,
                                         uint32_t b0, uint32_t b1) {
    asm volatile(
        "mma.sync.aligned.m16n8k16.row.col.f32.bf16.bf16.f32 "
        "{%0,%1,%2,%3}, {%4,%5,%6,%7}, {%8,%9}, {%0,%1,%2,%3};"
        : "+f"(c[0]), "+f"(c[1]), "+f"(c[2]), "+f"(c[3])
        : "r"(a0), "r"(a1), "r"(a2), "r"(a3), "r"(b0), "r"(b1));
}
__device__ __forceinline__ void cpasync16(uint32_t smem, const void* gptr) {
    asm volatile("cp.async.cg.shared.global [%0], [%1], 16;" :: "r"(smem), "l"(gptr) : "memory");
}
__device__ __forceinline__ void cp_commit() {
    asm volatile("cp.async.commit_group;" ::: "memory");
}
__device__ __forceinline__ void cp_wait1() {
    asm volatile("cp.async.wait_group 1;" ::: "memory");
}
__device__ __forceinline__ void cp_wait0() {
    asm volatile("cp.async.wait_group 0;" ::: "memory");
}

// ---------------- scratch ----------------------------------------------------
__device__ float g_xn[BB * SS * HH];
__device__ int   g_idx[BB * SS];
__device__ int   g_rank[BB * SS];
__device__ int   g_cnt[BB];

#define WO_OFF 393216
#define WALL   524288
__device__ uint32_t g_whi[WALL], g_wlo[WALL];
__device__ uint32_t g_xhi[BB * SS * 256], g_xlo[BB * SS * 256];
__device__ uint32_t g_ahi[BB * SS * 256], g_alo[BB * SS * 256];
__device__ uint32_t g_qhi[BB * NH * SS * 32], g_qlo[BB * NH * SS * 32];
__device__ uint32_t g_khi[BB * NH * SS * 32], g_klo[BB * NH * SS * 32];
__device__ uint32_t g_vhi[BB * NH * SS * 32], g_vlo[BB * NH * SS * 32];

// ---------------- 1) mask compaction + rank map -------------------------------
__global__ void compact_kernel(const int* __restrict__ mask) {
    int b = blockIdx.x;
    int t = threadIdx.x;
    int vals[8];
    int c = 0;
#pragma unroll
    for (int i = 0; i < 8; i++) {
        vals[i] = mask[(size_t)b * SS + t * 8 + i];
        c += (vals[i] != 0);
    }
    __shared__ int s[256];
    s[t] = c;
    __syncthreads();
    for (int off = 1; off < 256; off <<= 1) {
        int v = (t >= off) ? s[t - off] : 0;
        __syncthreads();
        s[t] += v;
        __syncthreads();
    }
    int pos = s[t] - c;
#pragma unroll
    for (int i = 0; i < 8; i++) {
        int orig = t * 8 + i;
        if (vals[i]) {
            g_idx[(size_t)b * SS + pos] = orig;
            g_rank[(size_t)b * SS + orig] = pos;
            pos++;
        } else {
            g_rank[(size_t)b * SS + orig] = -1;
        }
    }
    if (t == 255) g_cnt[b] = s[255];
}

// ---------------- 2) LayerNorm fused with convert + zeroing -------------------
__global__ void ln_kernel(const float* __restrict__ x,
                          const float* __restrict__ gamma,
                          const float* __restrict__ beta,
                          float* __restrict__ out) {
    int row = blockIdx.x;
    int t = threadIdx.x;
    const float* xr = x + (size_t)row * HH;
    float4 v = *(const float4*)(xr + t * 4);
    float s  = (v.x + v.y) + (v.z + v.w);
    float sq = (v.x * v.x + v.y * v.y) + (v.z * v.z + v.w * v.w);
    __shared__ float ssum[4], ssq[4];
    for (int o = 16; o > 0; o >>= 1) {
        s  += __shfl_xor_sync(0xffffffffu, s,  o);
        sq += __shfl_xor_sync(0xffffffffu, sq, o);
    }
    if ((t & 31) == 0) { ssum[t >> 5] = s; ssq[t >> 5] = sq; }
    __syncthreads();
    float tot  = (ssum[0] + ssum[1]) + (ssum[2] + ssum[3]);
    float totq = (ssq[0]  + ssq[1])  + (ssq[2]  + ssq[3]);
    float mu  = tot * (1.0f / HH);
    float var = totq * (1.0f / HH) - mu * mu;
    float inv = rsqrtf(var + 1e-5f);

    float4 gm = *(const float4*)(gamma + t * 4);
    float4 bt = *(const float4*)(beta  + t * 4);
    float y0 = (v.x - mu) * inv * gm.x + bt.x;
    float y1 = (v.y - mu) * inv * gm.y + bt.y;
    float y2 = (v.z - mu) * inv * gm.z + bt.z;
    float y3 = (v.w - mu) * inv * gm.w + bt.w;

    int rank = g_rank[row];
    if (rank >= 0) {
        *(float4*)(g_xn + (size_t)row * HH + t * 4) = make_float4(y0, y1, y2, y3);
        uint32_t h0, l0, h1, l1;
        pack_hl(y0, y1, h0, l0);
        pack_hl(y2, y3, h1, l1);
        int b = row >> 11;
        size_t o = ((size_t)(b * SS + rank)) * 256 + t * 2;
        g_xhi[o] = h0; g_xhi[o + 1] = h1;
        g_xlo[o] = l0; g_xlo[o + 1] = l1;
    } else {
        *(float4*)(out + (size_t)row * HH + t * 4) = make_float4(0.f, 0.f, 0.f, 0.f);
    }
}

// ---------------- 3) weight convert --------------------------------------------
__global__ void wcvt_kernel(const float* __restrict__ Wq, const float* __restrict__ Wk,
                            const float* __restrict__ Wv, const float* __restrict__ Wo) {
    int i = blockIdx.x * 256 + threadIdx.x;
    const float* src;
    int rem;
    if (i < WO_OFF) {
        int which = i / 131072;
        rem = i - which * 131072;
        src = (which == 0 ? Wq : (which == 1 ? Wk : Wv));
    } else {
        rem = i - WO_OFF;
        src = Wo;
    }
    float2 v = *(const float2*)(src + (size_t)rem * 2);
    uint32_t h, l;
    pack_hl(v.x, v.y, h, l);
    g_whi[i] = h;
    g_wlo[i] = l;
}

// ---------------- 4) QKV projection: cp.async double-buffered ------------------
#define QS_AHI 0
#define QS_ALO 9216
#define QS_WHI 18432
#define QS_WLO 27648
#define QS_STAGE 36864
#define QS_TOTAL (2 * QS_STAGE)

__global__ __launch_bounds__(128)
void qkv_mma_kernel() {
    extern __shared__ __align__(16) char smq[];
    int mt    = blockIdx.x;
    int which = blockIdx.y >> 5;
    int bn    = blockIdx.y & 31;
    int b = bn >> 3, n = bn & 7;
    int cnt = g_cnt[b];
    if (mt * 64 >= cnt) return;

    const uint32_t* Wh = g_whi + which * 131072 + n * 16384;
    const uint32_t* Wl = g_wlo + which * 131072 + n * 16384;
    uint32_t* Ch = (which == 0 ? g_qhi : (which == 1 ? g_khi : g_vhi)) + (size_t)bn * SS * 32;
    uint32_t* Cl = (which == 0 ? g_qlo : (which == 1 ? g_klo : g_vlo)) + (size_t)bn * SS * 32;

    uint32_t sb = (uint32_t)__cvta_generic_to_shared(smq);
    int tid  = threadIdx.x;
    int w    = tid >> 5;
    int lane = tid & 31;
    int g    = lane >> 2;
    int tig  = lane & 3;
    int laneq = lane & 15;
    int jsel  = lane >> 4;
    int arow = w * 16 + (lane & 7) + ((lane >> 3) & 1) * 8;
    int ad   = jsel * 8;
    int brow16 = (laneq & 7) + ((laneq >> 3) & 1) * 8;

    float acc[8][4];
#pragma unroll
    for (int i = 0; i < 8; i++)
#pragma unroll
        for (int j = 0; j < 4; j++) acc[i][j] = 0.f;

    int lrow  = tid >> 1;
    int lhalf = (tid & 1) * 16;
    const uint32_t* aH = g_xhi + ((size_t)b * SS + mt * 64 + lrow) * 256 + lhalf;
    const uint32_t* aL = g_xlo + ((size_t)b * SS + mt * 64 + lrow) * 256 + lhalf;
    uint32_t so_base = (uint32_t)(lrow * 36 + lhalf) * 4;

    // prologue: stage chunk 0 into buffer 0
    {
        const uint32_t* wH = Wh + (size_t)lrow * 32 + lhalf;
        const uint32_t* wL = Wl + (size_t)lrow * 32 + lhalf;
#pragma unroll
        for (int j = 0; j < 4; j++) {
            uint32_t so = so_base + 16 * j;
            cpasync16(sb + QS_AHI + so, aH + 4 * j);
            cpasync16(sb + QS_ALO + so, aL + 4 * j);
            cpasync16(sb + QS_WHI + so, wH + 4 * j);
            cpasync16(sb + QS_WLO + so, wL + 4 * j);
        }
        cp_commit();
    }

    for (int kc = 0; kc < 8; kc++) {
        if (kc < 7) {
            uint32_t st = sb + ((kc + 1) & 1) * QS_STAGE;
            const uint32_t* wH = Wh + (size_t)((kc + 1) * 64 + lrow) * 32 + lhalf;
            const uint32_t* wL = Wl + (size_t)((kc + 1) * 64 + lrow) * 32 + lhalf;
#pragma unroll
            for (int j = 0; j < 4; j++) {
                uint32_t so = so_base + 16 * j;
                cpasync16(st + QS_AHI + so, aH + (kc + 1) * 32 + 4 * j);
                cpasync16(st + QS_ALO + so, aL + (kc + 1) * 32 + 4 * j);
                cpasync16(st + QS_WHI + so, wH + 4 * j);
                cpasync16(st + QS_WLO + so, wL + 4 * j);
            }
            cp_commit();
            cp_wait1();
        } else {
            cp_wait0();
        }
        __syncthreads();
        uint32_t cbase = sb + (kc & 1) * QS_STAGE;
#pragma unroll
        for (int c = 0; c < 4; c++) {
            uint32_t aoff = (uint32_t)(arow * 72 + 16 * c + ad) * 2;
            uint32_t ah0, ah1, ah2, ah3, al0, al1, al2, al3;
            ldsm4(ah0, ah1, ah2, ah3, cbase + QS_AHI + aoff);
            ldsm4(al0, al1, al2, al3, cbase + QS_ALO + aoff);
#pragma unroll
            for (int ntp = 0; ntp < 4; ntp++) {
                uint32_t boff = (uint32_t)((16 * c + brow16) * 72 + 16 * ntp + 8 * jsel) * 2;
                uint32_t bh0, bh1, bh2, bh3, bl0, bl1, bl2, bl3;
                ldsm4t(bh0, bh1, bh2, bh3, cbase + QS_WHI + boff);
                ldsm4t(bl0, bl1, bl2, bl3, cbase + QS_WLO + boff);
                mma_bf16(acc[2 * ntp],     ah0, ah1, ah2, ah3, bh0, bh1);
                mma_bf16(acc[2 * ntp],     al0, al1, al2, al3, bh0, bh1);
                mma_bf16(acc[2 * ntp],     ah0, ah1, ah2, ah3, bl0, bl1);
                mma_bf16(acc[2 * ntp + 1], ah0, ah1, ah2, ah3, bh2, bh3);
                mma_bf16(acc[2 * ntp + 1], al0, al1, al2, al3, bh2, bh3);
                mma_bf16(acc[2 * ntp + 1], ah0, ah1, ah2, ah3, bl2, bl3);
            }
        }
        __syncthreads();
    }
    int r0 = mt * 64 + w * 16 + g;
    int r1 = r0 + 8;
#pragma unroll
    for (int nt = 0; nt < 8; nt++) {
        int ci = nt * 4 + tig;
        if (r0 < cnt) {
            uint32_t h, l;
            pack_hl(acc[nt][0], acc[nt][1], h, l);
            Ch[(size_t)r0 * 32 + ci] = h;
            Cl[(size_t)r0 * 32 + ci] = l;
        }
        if (r1 < cnt) {
            uint32_t h, l;
            pack_hl(acc[nt][2], acc[nt][3], h, l);
            Ch[(size_t)r1 * 32 + ci] = h;
            Cl[(size_t)r1 * 32 + ci] = l;
        }
    }
}

// ---------------- 5) attention: mma.sync bf16-split (R10 verbatim) -------------
#define APAD 72
#define OFF_QHI 0
#define OFF_QLO 9216
#define OFF_KHI 18432
#define OFF_KLO 27648
#define OFF_VHI 36864
#define OFF_VLO 46080
#define SMA_TOTAL 55296

__global__ __launch_bounds__(128)
void attn_kernel() {
    extern __shared__ __align__(16) char sm[];
    int bn = blockIdx.y;
    int b  = bn >> 3;
    int n  = bn & 7;
    int cnt = g_cnt[b];
    int qbase = blockIdx.x * 64;
    if (qbase >= cnt) return;

    int tid  = threadIdx.x;
    int w    = tid >> 5;
    int lane = tid & 31;
    int g    = lane >> 2;
    int tig  = lane & 3;
    uint32_t sb = (uint32_t)__cvta_generic_to_shared(sm);

    {
        int row   = tid >> 1;
        int half  = tid & 1;
        const uint4* qh = (const uint4*)(g_qhi + ((size_t)bn * SS + qbase + row) * 32 + half * 16);
        const uint4* ql = (const uint4*)(g_qlo + ((size_t)bn * SS + qbase + row) * 32 + half * 16);
        uint32_t off = (uint32_t)row * 144 + half * 64;
#pragma unroll
        for (int j = 0; j < 4; j++) {
            *(uint4*)(sm + OFF_QHI + off + j * 16) = qh[j];
            *(uint4*)(sm + OFF_QLO + off + j * 16) = ql[j];
        }
    }

    float o[8][4];
#pragma unroll
    for (int i = 0; i < 8; i++)
#pragma unroll
        for (int j = 0; j < 4; j++) o[i][j] = 0.f;
    float l0 = 0.f, l1 = 0.f;

    int q0 = w * 16;
    int arow_q = q0 + (lane & 7) + ((lane >> 3) & 1) * 8;
    int ad_sel = (lane >> 4) * 8;
    int brow   = lane & 7;
    int bsel   = ((lane >> 3) & 1) * 8;

    int ktiles = (cnt + 63) >> 6;
    for (int kt = 0; kt < ktiles; kt++) {
        int kbase = kt * 64;
        __syncthreads();
        {
            int row  = tid >> 1;
            int half = tid & 1;
            size_t gsrc = ((size_t)bn * SS + kbase + row) * 32 + half * 16;
            const uint4* kh = (const uint4*)(g_khi + gsrc);
            const uint4* kl = (const uint4*)(g_klo + gsrc);
            const uint4* vh = (const uint4*)(g_vhi + gsrc);
            const uint4* vl = (const uint4*)(g_vlo + gsrc);
            uint32_t off = (uint32_t)row * 144 + half * 64;
#pragma unroll
            for (int j = 0; j < 4; j++) {
                *(uint4*)(sm + OFF_KHI + off + j * 16) = kh[j];
                *(uint4*)(sm + OFF_KLO + off + j * 16) = kl[j];
                *(uint4*)(sm + OFF_VHI + off + j * 16) = vh[j];
                *(uint4*)(sm + OFF_VLO + off + j * 16) = vl[j];
            }
        }
        __syncthreads();

        float s[8][4];
#pragma unroll
        for (int i = 0; i < 8; i++)
#pragma unroll
            for (int j = 0; j < 4; j++) s[i][j] = 0.f;

#pragma unroll
        for (int c = 0; c < 4; c++) {
            uint32_t aoffq = (uint32_t)(arow_q * APAD + 16 * c + ad_sel) * 2;
            uint32_t ah0, ah1, ah2, ah3, al0, al1, al2, al3;
            ldsm4(ah0, ah1, ah2, ah3, sb + OFF_QHI + aoffq);
            ldsm4(al0, al1, al2, al3, sb + OFF_QLO + aoffq);
#pragma unroll
            for (int j = 0; j < 8; j++) {
                uint32_t boff = (uint32_t)((8 * j + brow) * APAD + 16 * c + bsel) * 2;
                uint32_t bh0, bh1, bl0, bl1;
                ldsm2(bh0, bh1, sb + OFF_KHI + boff);
                ldsm2(bl0, bl1, sb + OFF_KLO + boff);
                mma_bf16(s[j], ah0, ah1, ah2, ah3, bh0, bh1);
                mma_bf16(s[j], al0, al1, al2, al3, bh0, bh1);
                mma_bf16(s[j], ah0, ah1, ah2, ah3, bl0, bl1);
            }
        }

#pragma unroll
        for (int j = 0; j < 8; j++) {
            int kg0 = kbase + 8 * j + 2 * tig;
#pragma unroll
            for (int r = 0; r < 4; r++) {
                int kg = kg0 + (r & 1);
                float p = (kg < cnt) ? __expf(s[j][r] * 0.125f) : 0.f;
                s[j][r] = p;
                if (r < 2) l0 += p; else l1 += p;
            }
        }

#pragma unroll
        for (int c = 0; c < 4; c++) {
            uint32_t ph0, ph1, ph2, ph3, pl0, pl1, pl2, pl3;
            pack_hl(s[2 * c][0],     s[2 * c][1],     ph0, pl0);
            pack_hl(s[2 * c][2],     s[2 * c][3],     ph1, pl1);
            pack_hl(s[2 * c + 1][0], s[2 * c + 1][1], ph2, pl2);
            pack_hl(s[2 * c + 1][2], s[2 * c + 1][3], ph3, pl3);
#pragma unroll
            for (int dt = 0; dt < 8; dt++) {
                uint32_t voff = (uint32_t)((16 * c + bsel + brow) * APAD + 8 * dt) * 2;
                uint32_t vh0, vh1, vl0, vl1;
                ldsm2t(vh0, vh1, sb + OFF_VHI + voff);
                ldsm2t(vl0, vl1, sb + OFF_VLO + voff);
                mma_bf16(o[dt], ph0, ph1, ph2, ph3, vh0, vh1);
                mma_bf16(o[dt], pl0, pl1, pl2, pl3, vh0, vh1);
                mma_bf16(o[dt], ph0, ph1, ph2, ph3, vl0, vl1);
            }
        }
    }

    l0 += __shfl_xor_sync(0xffffffffu, l0, 1);
    l0 += __shfl_xor_sync(0xffffffffu, l0, 2);
    l1 += __shfl_xor_sync(0xffffffffu, l1, 1);
    l1 += __shfl_xor_sync(0xffffffffu, l1, 2);
    float inv0 = 1.0f / l0;
    float inv1 = 1.0f / l1;

    int r0 = qbase + q0 + g;
    int r1 = r0 + 8;
#pragma unroll
    for (int dt = 0; dt < 8; dt++) {
        int cu = n * 32 + dt * 4 + tig;
        if (r0 < cnt) {
            uint32_t h, l;
            pack_hl(o[dt][0] * inv0, o[dt][1] * inv0, h, l);
            g_ahi[((size_t)b * SS + r0) * 256 + cu] = h;
            g_alo[((size_t)b * SS + r0) * 256 + cu] = l;
        }
        if (r1 < cnt) {
            uint32_t h, l;
            pack_hl(o[dt][2] * inv1, o[dt][3] * inv1, h, l);
            g_ahi[((size_t)b * SS + r1) * 256 + cu] = h;
            g_alo[((size_t)b * SS + r1) * 256 + cu] = l;
        }
    }
}

// ---------------- 6) out projection: cp.async double-buffered ------------------
__global__ __launch_bounds__(128)
void outproj_mma_kernel(float* __restrict__ out) {
    extern __shared__ __align__(16) char smq[];
    int ntb = blockIdx.x;
    int b   = blockIdx.y >> 5;
    int mt  = blockIdx.y & 31;
    int cnt = g_cnt[b];
    if (mt * 64 >= cnt) return;

    uint32_t sb = (uint32_t)__cvta_generic_to_shared(smq);
    int tid  = threadIdx.x;
    int w    = tid >> 5;
    int lane = tid & 31;
    int g    = lane >> 2;
    int tig  = lane & 3;
    int laneq = lane & 15;
    int jsel  = lane >> 4;
    int arow = w * 16 + (lane & 7) + ((lane >> 3) & 1) * 8;
    int ad   = jsel * 8;
    int brow16 = (laneq & 7) + ((laneq >> 3) & 1) * 8;

    float acc[8][4];
#pragma unroll
    for (int i = 0; i < 8; i++)
#pragma unroll
        for (int j = 0; j < 4; j++) acc[i][j] = 0.f;

    int lrow  = tid >> 1;
    int lhalf = (tid & 1) * 16;
    const uint32_t* aH = g_ahi + ((size_t)b * SS + mt * 64 + lrow) * 256 + lhalf;
    const uint32_t* aL = g_alo + ((size_t)b * SS + mt * 64 + lrow) * 256 + lhalf;
    const uint32_t* WhBase = g_whi + WO_OFF + (size_t)lrow * 256 + ntb * 32 + lhalf;
    const uint32_t* WlBase = g_wlo + WO_OFF + (size_t)lrow * 256 + ntb * 32 + lhalf;
    uint32_t so_base = (uint32_t)(lrow * 36 + lhalf) * 4;

    {
#pragma unroll
        for (int j = 0; j < 4; j++) {
            uint32_t so = so_base + 16 * j;
            cpasync16(sb + QS_AHI + so, aH + 4 * j);
            cpasync16(sb + QS_ALO + so, aL + 4 * j);
            cpasync16(sb + QS_WHI + so, WhBase + 4 * j);
            cpasync16(sb + QS_WLO + so, WlBase + 4 * j);
        }
        cp_commit();
    }

    for (int kc = 0; kc < 8; kc++) {
        if (kc < 7) {
            uint32_t st = sb + ((kc + 1) & 1) * QS_STAGE;
            size_t woff = (size_t)(kc + 1) * 64 * 256;
#pragma unroll
            for (int j = 0; j < 4; j++) {
                uint32_t so = so_base + 16 * j;
                cpasync16(st + QS_AHI + so, aH + (kc + 1) * 32 + 4 * j);
                cpasync16(st + QS_ALO + so, aL + (kc + 1) * 32 + 4 * j);
                cpasync16(st + QS_WHI + so, WhBase + woff + 4 * j);
                cpasync16(st + QS_WLO + so, WlBase + woff + 4 * j);
            }
            cp_commit();
            cp_wait1();
        } else {
            cp_wait0();
        }
        __syncthreads();
        uint32_t cbase = sb + (kc & 1) * QS_STAGE;
#pragma unroll
        for (int c = 0; c < 4; c++) {
            uint32_t aoff = (uint32_t)(arow * 72 + 16 * c + ad) * 2;
            uint32_t ah0, ah1, ah2, ah3, al0, al1, al2, al3;
            ldsm4(ah0, ah1, ah2, ah3, cbase + QS_AHI + aoff);
            ldsm4(al0, al1, al2, al3, cbase + QS_ALO + aoff);
#pragma unroll
            for (int ntp = 0; ntp < 4; ntp++) {
                uint32_t boff = (uint32_t)((16 * c + brow16) * 72 + 16 * ntp + 8 * jsel) * 2;
                uint32_t bh0, bh1, bh2, bh3, bl0, bl1, bl2, bl3;
                ldsm4t(bh0, bh1, bh2, bh3, cbase + QS_WHI + boff);
                ldsm4t(bl0, bl1, bl2, bl3, cbase + QS_WLO + boff);
                mma_bf16(acc[2 * ntp],     ah0, ah1, ah2, ah3, bh0, bh1);
                mma_bf16(acc[2 * ntp],     al0, al1, al2, al3, bh0, bh1);
                mma_bf16(acc[2 * ntp],     ah0, ah1, ah2, ah3, bl0, bl1);
                mma_bf16(acc[2 * ntp + 1], ah0, ah1, ah2, ah3, bh2, bh3);
                mma_bf16(acc[2 * ntp + 1], al0, al1, al2, al3, bh2, bh3);
                mma_bf16(acc[2 * ntp + 1], ah0, ah1, ah2, ah3, bl2, bl3);
            }
        }
        __syncthreads();
    }
    int r0 = mt * 64 + w * 16 + g;
    int r1 = r0 + 8;
#pragma unroll
    for (int nt = 0; nt < 8; nt++) {
        int col = ntb * 64 + nt * 8 + 2 * tig;
        if (r0 < cnt) {
            int orig = g_idx[(size_t)b * SS + r0];
            size_t off = ((size_t)b * SS + orig) * HH + col;
            float2 xv = *(const float2*)(g_xn + off);
            *(float2*)(out + off) = make_float2(acc[nt][0] + xv.x, acc[nt][1] + xv.y);
        }
        if (r1 < cnt) {
            int orig = g_idx[(size_t)b * SS + r1];
            size_t off = ((size_t)b * SS + orig) * HH + col;
            float2 xv = *(const float2*)(g_xn + off);
            *(float2*)(out + off) = make_float2(acc[nt][2] + xv.x, acc[nt][3] + xv.y);
        }
    }
}

// ---------------- launch ------------------------------------------------------
extern "C" void kernel_launch(void* const* d_in, const int* in_sizes, int n_in,
                              void* d_out, int out_size) {
    const float* x     = (const float*)d_in[0];
    const int*   mask  = (const int*)  d_in[1];
    const float* Wq    = (const float*)d_in[2];
    const float* Wk    = (const float*)d_in[3];
    const float* Wv    = (const float*)d_in[4];
    const float* Wo    = (const float*)d_in[5];
    const float* gamma = (const float*)d_in[6];
    const float* beta  = (const float*)d_in[7];
    float* out = (float*)d_out;

    cudaFuncSetAttribute(attn_kernel,
                         cudaFuncAttributeMaxDynamicSharedMemorySize, SMA_TOTAL);
    cudaFuncSetAttribute(qkv_mma_kernel,
                         cudaFuncAttributeMaxDynamicSharedMemorySize, QS_TOTAL);
    cudaFuncSetAttribute(outproj_mma_kernel,
                         cudaFuncAttributeMaxDynamicSharedMemorySize, QS_TOTAL);

    compact_kernel<<<BB, 256>>>(mask);
    ln_kernel<<<BB * SS, 128>>>(x, gamma, beta, out);
    wcvt_kernel<<<WALL / 256, 256>>>(Wq, Wk, Wv, Wo);
    qkv_mma_kernel<<<dim3(32, 96), 128, QS_TOTAL>>>();
    attn_kernel<<<dim3(SS / 64, BB * NH), 128, SMA_TOTAL>>>();
    outproj_mma_kernel<<<dim3(8, BB * 32), 128, QS_TOTAL>>>(out);
}

// round 14
// speedup vs baseline: 1.4834x; 1.4834x over previous
#include <cuda_runtime.h>
#include <cuda_fp16.h>
#include <math.h>
#include <stdint.h>

#define BB 4
#define SS 2048
#define HH 512
#define NH 8
#define DKK 64

// ---------------- fp16 split + mma.sync helpers (baseline PTX) ---------------
__device__ __forceinline__ uint32_t pack_h(float e0, float e1) {
    __half2 hh = __floats2half2_rn(e0, e1);
    return *(uint32_t*)&hh;
}
__device__ __forceinline__ void pack_hl(float e0, float e1, uint32_t& h, uint32_t& l) {
    __half2 hh = __floats2half2_rn(e0, e1);
    h = *(uint32_t*)&hh;
    float a = __half2float(__low2half(hh));
    float b = __half2float(__high2half(hh));
    __half2 ll = __floats2half2_rn(e0 - a, e1 - b);
    l = *(uint32_t*)&ll;
}
__device__ __forceinline__ void ldsm4(uint32_t& r0, uint32_t& r1, uint32_t& r2, uint32_t& r3,
                                      uint32_t a) {
    asm volatile("ldmatrix.sync.aligned.m8n8.x4.shared.b16 {%0,%1,%2,%3}, [%4];"
                 : "=r"(r0), "=r"(r1), "=r"(r2), "=r"(r3) : "r"(a));
}
__device__ __forceinline__ void ldsm2(uint32_t& r0, uint32_t& r1, uint32_t a) {
    asm volatile("ldmatrix.sync.aligned.m8n8.x2.shared.b16 {%0,%1}, [%2];"
                 : "=r"(r0), "=r"(r1) : "r"(a));
}
__device__ __forceinline__ void ldsm2t(uint32_t& r0, uint32_t& r1, uint32_t a) {
    asm volatile("ldmatrix.sync.aligned.m8n8.x2.trans.shared.b16 {%0,%1}, [%2];"
                 : "=r"(r0), "=r"(r1) : "r"(a));
}
__device__ __forceinline__ void ldsm4t(uint32_t& r0, uint32_t& r1, uint32_t& r2, uint32_t& r3,
                                       uint32_t a) {
    asm volatile("ldmatrix.sync.aligned.m8n8.x4.trans.shared.b16 {%0,%1,%2,%3}, [%4];"
                 : "=r"(r0), "=r"(r1), "=r"(r2), "=r"(r3) : "r"(a));
}
__device__ __forceinline__ void mma_f16(float* c, uint32_t a0, uint32_t a1,
                                        uint32_t a2, uint32_t a3,
                                        uint32_t b0, uint32_t b1) {
    asm volatile(
        "mma.sync.aligned.m16n8k16.row.col.f32.f16.f16.f32 "
        "{%0,%1,%2,%3}, {%4,%5,%6,%7}, {%8,%9}, {%0,%1,%2,%3};"
        : "+f"(c[0]), "+f"(c[1]), "+f"(c[2]), "+f"(c[3])
        : "r"(a0), "r"(a1), "r"(a2), "r"(a3), "r"(b0), "r"(b1));
}

// ---------------- scratch ----------------------------------------------------
__device__ float g_xn[BB * SS * HH];
__device__ int   g_idx[BB * SS];
__device__ int   g_rank[BB * SS];
__device__ int   g_cnt[BB];

#define WO_OFF 393216
#define WALL   524288
__device__ uint32_t g_whi[WALL];                                  // fp16 pairs, hi only
__device__ uint32_t g_xhi[BB * SS * 256], g_xlo[BB * SS * 256];   // compacted xn split
__device__ uint32_t g_ahi[BB * SS * 256], g_alo[BB * SS * 256];   // attn out split
__device__ uint32_t g_qhi[BB * NH * SS * 32], g_qlo[BB * NH * SS * 32];  // q split
__device__ uint32_t g_khi[BB * NH * SS * 32];                     // k hi only (B-side)
__device__ uint32_t g_vhi[BB * NH * SS * 32];                     // v hi only (B-side)

// ---------------- 1) mask compaction + rank map -------------------------------
__global__ void compact_kernel(const int* __restrict__ mask) {
    int b = blockIdx.x;
    int t = threadIdx.x;
    int vals[8];
    int c = 0;
#pragma unroll
    for (int i = 0; i < 8; i++) {
        vals[i] = mask[(size_t)b * SS + t * 8 + i];
        c += (vals[i] != 0);
    }
    __shared__ int s[256];
    s[t] = c;
    __syncthreads();
    for (int off = 1; off < 256; off <<= 1) {
        int v = (t >= off) ? s[t - off] : 0;
        __syncthreads();
        s[t] += v;
        __syncthreads();
    }
    int pos = s[t] - c;
#pragma unroll
    for (int i = 0; i < 8; i++) {
        int orig = t * 8 + i;
        if (vals[i]) {
            g_idx[(size_t)b * SS + pos] = orig;
            g_rank[(size_t)b * SS + orig] = pos;
            pos++;
        } else {
            g_rank[(size_t)b * SS + orig] = -1;
        }
    }
    if (t == 255) g_cnt[b] = s[255];
}

// ---------------- 2) LayerNorm fused with convert + zeroing -------------------
__global__ void ln_kernel(const float* __restrict__ x,
                          const float* __restrict__ gamma,
                          const float* __restrict__ beta,
                          float* __restrict__ out) {
    int row = blockIdx.x;
    int t = threadIdx.x;
    const float* xr = x + (size_t)row * HH;
    float4 v = *(const float4*)(xr + t * 4);
    float s  = (v.x + v.y) + (v.z + v.w);
    float sq = (v.x * v.x + v.y * v.y) + (v.z * v.z + v.w * v.w);
    __shared__ float ssum[4], ssq[4];
    for (int o = 16; o > 0; o >>= 1) {
        s  += __shfl_xor_sync(0xffffffffu, s,  o);
        sq += __shfl_xor_sync(0xffffffffu, sq, o);
    }
    if ((t & 31) == 0) { ssum[t >> 5] = s; ssq[t >> 5] = sq; }
    __syncthreads();
    float tot  = (ssum[0] + ssum[1]) + (ssum[2] + ssum[3]);
    float totq = (ssq[0]  + ssq[1])  + (ssq[2]  + ssq[3]);
    float mu  = tot * (1.0f / HH);
    float var = totq * (1.0f / HH) - mu * mu;
    float inv = rsqrtf(var + 1e-5f);

    float4 gm = *(const float4*)(gamma + t * 4);
    float4 bt = *(const float4*)(beta  + t * 4);
    float y0 = (v.x - mu) * inv * gm.x + bt.x;
    float y1 = (v.y - mu) * inv * gm.y + bt.y;
    float y2 = (v.z - mu) * inv * gm.z + bt.z;
    float y3 = (v.w - mu) * inv * gm.w + bt.w;

    int rank = g_rank[row];
    if (rank >= 0) {
        *(float4*)(g_xn + (size_t)row * HH + t * 4) = make_float4(y0, y1, y2, y3);
        uint32_t h0, l0, h1, l1;
        pack_hl(y0, y1, h0, l0);
        pack_hl(y2, y3, h1, l1);
        int b = row >> 11;
        size_t o = ((size_t)(b * SS + rank)) * 256 + t * 2;
        g_xhi[o] = h0; g_xhi[o + 1] = h1;
        g_xlo[o] = l0; g_xlo[o + 1] = l1;
    } else {
        *(float4*)(out + (size_t)row * HH + t * 4) = make_float4(0.f, 0.f, 0.f, 0.f);
    }
}

// ---------------- 3) weight convert (hi only) ----------------------------------
__global__ void wcvt_kernel(const float* __restrict__ Wq, const float* __restrict__ Wk,
                            const float* __restrict__ Wv, const float* __restrict__ Wo) {
    int i = blockIdx.x * 256 + threadIdx.x;
    const float* src;
    int rem;
    if (i < WO_OFF) {
        int which = i / 131072;
        rem = i - which * 131072;
        src = (which == 0 ? Wq : (which == 1 ? Wk : Wv));
    } else {
        rem = i - WO_OFF;
        src = Wo;
    }
    float2 v = *(const float2*)(src + (size_t)rem * 2);
    g_whi[i] = pack_h(v.x, v.y);
}

// ---------------- 4) QKV projection: fp16 2-term, x4 B loads -------------------
__global__ __launch_bounds__(128)
void qkv_mma_kernel() {
    int mt    = blockIdx.x;
    int which = blockIdx.y >> 5;
    int bn    = blockIdx.y & 31;
    int b = bn >> 3, n = bn & 7;
    int cnt = g_cnt[b];
    if (mt * 64 >= cnt) return;

    const uint32_t* Wh = g_whi + which * 131072 + n * 16384;
    uint32_t* Ch = (which == 0 ? g_qhi : (which == 1 ? g_khi : g_vhi)) + (size_t)bn * SS * 32;
    uint32_t* Cl = (which == 0) ? (g_qlo + (size_t)bn * SS * 32) : nullptr;

    __shared__ __align__(16) uint32_t sAhi[64 * 36], sAlo[64 * 36];
    __shared__ __align__(16) uint32_t sWhi[64 * 36];

    int tid  = threadIdx.x;
    int w    = tid >> 5;
    int lane = tid & 31;
    int g    = lane >> 2;
    int tig  = lane & 3;
    int laneq = lane & 15;
    int jsel  = lane >> 4;
    int arow = w * 16 + (lane & 7) + ((lane >> 3) & 1) * 8;
    int ad   = jsel * 8;
    int brow16 = (laneq & 7) + ((laneq >> 3) & 1) * 8;

    uint32_t bAhi = (uint32_t)__cvta_generic_to_shared(sAhi);
    uint32_t bAlo = (uint32_t)__cvta_generic_to_shared(sAlo);
    uint32_t bWhi = (uint32_t)__cvta_generic_to_shared(sWhi);

    float acc[8][4];
#pragma unroll
    for (int i = 0; i < 8; i++)
#pragma unroll
        for (int j = 0; j < 4; j++) acc[i][j] = 0.f;

    int lrow  = tid >> 1;
    int lhalf = (tid & 1) * 16;
    const uint32_t* aH = g_xhi + ((size_t)b * SS + mt * 64 + lrow) * 256 + lhalf;
    const uint32_t* aL = g_xlo + ((size_t)b * SS + mt * 64 + lrow) * 256 + lhalf;

    for (int kc = 0; kc < 8; kc++) {
        __syncthreads();
        const uint32_t* wH = Wh + (kc * 64 + lrow) * 32 + lhalf;
#pragma unroll
        for (int j = 0; j < 4; j++) {
            *(uint4*)&sAhi[lrow * 36 + lhalf + 4 * j] = *(const uint4*)(aH + kc * 32 + 4 * j);
            *(uint4*)&sAlo[lrow * 36 + lhalf + 4 * j] = *(const uint4*)(aL + kc * 32 + 4 * j);
            *(uint4*)&sWhi[lrow * 36 + lhalf + 4 * j] = *(const uint4*)(wH + 4 * j);
        }
        __syncthreads();
#pragma unroll
        for (int c = 0; c < 4; c++) {
            uint32_t aoff = (uint32_t)(arow * 72 + 16 * c + ad) * 2;
            uint32_t ah0, ah1, ah2, ah3, al0, al1, al2, al3;
            ldsm4(ah0, ah1, ah2, ah3, bAhi + aoff);
            ldsm4(al0, al1, al2, al3, bAlo + aoff);
#pragma unroll
            for (int ntp = 0; ntp < 4; ntp++) {
                uint32_t boff = (uint32_t)((16 * c + brow16) * 72 + 16 * ntp + 8 * jsel) * 2;
                uint32_t bh0, bh1, bh2, bh3;
                ldsm4t(bh0, bh1, bh2, bh3, bWhi + boff);
                mma_f16(acc[2 * ntp],     ah0, ah1, ah2, ah3, bh0, bh1);
                mma_f16(acc[2 * ntp],     al0, al1, al2, al3, bh0, bh1);
                mma_f16(acc[2 * ntp + 1], ah0, ah1, ah2, ah3, bh2, bh3);
                mma_f16(acc[2 * ntp + 1], al0, al1, al2, al3, bh2, bh3);
            }
        }
    }
    int r0 = mt * 64 + w * 16 + g;
    int r1 = r0 + 8;
#pragma unroll
    for (int nt = 0; nt < 8; nt++) {
        int ci = nt * 4 + tig;
        if (r0 < cnt) {
            if (which == 0) {
                uint32_t h, l;
                pack_hl(acc[nt][0], acc[nt][1], h, l);
                Ch[(size_t)r0 * 32 + ci] = h;
                Cl[(size_t)r0 * 32 + ci] = l;
            } else {
                Ch[(size_t)r0 * 32 + ci] = pack_h(acc[nt][0], acc[nt][1]);
            }
        }
        if (r1 < cnt) {
            if (which == 0) {
                uint32_t h, l;
                pack_hl(acc[nt][2], acc[nt][3], h, l);
                Ch[(size_t)r1 * 32 + ci] = h;
                Cl[(size_t)r1 * 32 + ci] = l;
            } else {
                Ch[(size_t)r1 * 32 + ci] = pack_h(acc[nt][2], acc[nt][3]);
            }
        }
    }
}

// ---------------- 5) attention: fp16 2-term ------------------------------------
#define APAD 72
#define OFF_QHI 0
#define OFF_QLO 9216
#define OFF_KHI 18432
#define OFF_VHI 27648
#define SMA_TOTAL 36864

__global__ __launch_bounds__(128)
void attn_kernel() {
    extern __shared__ __align__(16) char sm[];
    int bn = blockIdx.y;
    int b  = bn >> 3;
    int n  = bn & 7;
    int cnt = g_cnt[b];
    int qbase = blockIdx.x * 64;
    if (qbase >= cnt) return;

    int tid  = threadIdx.x;
    int w    = tid >> 5;
    int lane = tid & 31;
    int g    = lane >> 2;
    int tig  = lane & 3;
    uint32_t sb = (uint32_t)__cvta_generic_to_shared(sm);

    {
        int row   = tid >> 1;
        int half  = tid & 1;
        const uint4* qh = (const uint4*)(g_qhi + ((size_t)bn * SS + qbase + row) * 32 + half * 16);
        const uint4* ql = (const uint4*)(g_qlo + ((size_t)bn * SS + qbase + row) * 32 + half * 16);
        uint32_t off = (uint32_t)row * 144 + half * 64;
#pragma unroll
        for (int j = 0; j < 4; j++) {
            *(uint4*)(sm + OFF_QHI + off + j * 16) = qh[j];
            *(uint4*)(sm + OFF_QLO + off + j * 16) = ql[j];
        }
    }

    float o[8][4];
#pragma unroll
    for (int i = 0; i < 8; i++)
#pragma unroll
        for (int j = 0; j < 4; j++) o[i][j] = 0.f;
    float l0 = 0.f, l1 = 0.f;

    int q0 = w * 16;
    int arow_q = q0 + (lane & 7) + ((lane >> 3) & 1) * 8;
    int ad_sel = (lane >> 4) * 8;
    int brow   = lane & 7;
    int bsel   = ((lane >> 3) & 1) * 8;

    int ktiles = (cnt + 63) >> 6;
    for (int kt = 0; kt < ktiles; kt++) {
        int kbase = kt * 64;
        __syncthreads();
        {
            int row  = tid >> 1;
            int half = tid & 1;
            size_t gsrc = ((size_t)bn * SS + kbase + row) * 32 + half * 16;
            const uint4* kh = (const uint4*)(g_khi + gsrc);
            const uint4* vh = (const uint4*)(g_vhi + gsrc);
            uint32_t off = (uint32_t)row * 144 + half * 64;
#pragma unroll
            for (int j = 0; j < 4; j++) {
                *(uint4*)(sm + OFF_KHI + off + j * 16) = kh[j];
                *(uint4*)(sm + OFF_VHI + off + j * 16) = vh[j];
            }
        }
        __syncthreads();

        float s[8][4];
#pragma unroll
        for (int i = 0; i < 8; i++)
#pragma unroll
            for (int j = 0; j < 4; j++) s[i][j] = 0.f;

#pragma unroll
        for (int c = 0; c < 4; c++) {
            uint32_t aoffq = (uint32_t)(arow_q * APAD + 16 * c + ad_sel) * 2;
            uint32_t ah0, ah1, ah2, ah3, al0, al1, al2, al3;
            ldsm4(ah0, ah1, ah2, ah3, sb + OFF_QHI + aoffq);
            ldsm4(al0, al1, al2, al3, sb + OFF_QLO + aoffq);
#pragma unroll
            for (int j = 0; j < 8; j++) {
                uint32_t boff = (uint32_t)((8 * j + brow) * APAD + 16 * c + bsel) * 2;
                uint32_t bh0, bh1;
                ldsm2(bh0, bh1, sb + OFF_KHI + boff);
                mma_f16(s[j], ah0, ah1, ah2, ah3, bh0, bh1);
                mma_f16(s[j], al0, al1, al2, al3, bh0, bh1);
            }
        }

#pragma unroll
        for (int j = 0; j < 8; j++) {
            int kg0 = kbase + 8 * j + 2 * tig;
#pragma unroll
            for (int r = 0; r < 4; r++) {
                int kg = kg0 + (r & 1);
                float p = (kg < cnt) ? __expf(s[j][r] * 0.125f) : 0.f;
                s[j][r] = p;
                if (r < 2) l0 += p; else l1 += p;
            }
        }

#pragma unroll
        for (int c = 0; c < 4; c++) {
            uint32_t ph0, ph1, ph2, ph3, pl0, pl1, pl2, pl3;
            pack_hl(s[2 * c][0],     s[2 * c][1],     ph0, pl0);
            pack_hl(s[2 * c][2],     s[2 * c][3],     ph1, pl1);
            pack_hl(s[2 * c + 1][0], s[2 * c + 1][1], ph2, pl2);
            pack_hl(s[2 * c + 1][2], s[2 * c + 1][3], ph3, pl3);
#pragma unroll
            for (int dt = 0; dt < 8; dt++) {
                uint32_t voff = (uint32_t)((16 * c + bsel + brow) * APAD + 8 * dt) * 2;
                uint32_t vh0, vh1;
                ldsm2t(vh0, vh1, sb + OFF_VHI + voff);
                mma_f16(o[dt], ph0, ph1, ph2, ph3, vh0, vh1);
                mma_f16(o[dt], pl0, pl1, pl2, pl3, vh0, vh1);
            }
        }
    }

    l0 += __shfl_xor_sync(0xffffffffu, l0, 1);
    l0 += __shfl_xor_sync(0xffffffffu, l0, 2);
    l1 += __shfl_xor_sync(0xffffffffu, l1, 1);
    l1 += __shfl_xor_sync(0xffffffffu, l1, 2);
    float inv0 = 1.0f / l0;
    float inv1 = 1.0f / l1;

    int r0 = qbase + q0 + g;
    int r1 = r0 + 8;
#pragma unroll
    for (int dt = 0; dt < 8; dt++) {
        int cu = n * 32 + dt * 4 + tig;
        if (r0 < cnt) {
            uint32_t h, l;
            pack_hl(o[dt][0] * inv0, o[dt][1] * inv0, h, l);
            g_ahi[((size_t)b * SS + r0) * 256 + cu] = h;
            g_alo[((size_t)b * SS + r0) * 256 + cu] = l;
        }
        if (r1 < cnt) {
            uint32_t h, l;
            pack_hl(o[dt][2] * inv1, o[dt][3] * inv1, h, l);
            g_ahi[((size_t)b * SS + r1) * 256 + cu] = h;
            g_alo[((size_t)b * SS + r1) * 256 + cu] = l;
        }
    }
}

// ---------------- 6) out projection: fp16 2-term, x4 B loads -------------------
__global__ __launch_bounds__(128)
void outproj_mma_kernel(float* __restrict__ out) {
    int ntb = blockIdx.x;
    int b   = blockIdx.y >> 5;
    int mt  = blockIdx.y & 31;
    int cnt = g_cnt[b];
    if (mt * 64 >= cnt) return;

    __shared__ __align__(16) uint32_t sAhi[64 * 36], sAlo[64 * 36];
    __shared__ __align__(16) uint32_t sWhi[64 * 36];

    int tid  = threadIdx.x;
    int w    = tid >> 5;
    int lane = tid & 31;
    int g    = lane >> 2;
    int tig  = lane & 3;
    int laneq = lane & 15;
    int jsel  = lane >> 4;
    int arow = w * 16 + (lane & 7) + ((lane >> 3) & 1) * 8;
    int ad   = jsel * 8;
    int brow16 = (laneq & 7) + ((laneq >> 3) & 1) * 8;

    uint32_t bAhi = (uint32_t)__cvta_generic_to_shared(sAhi);
    uint32_t bAlo = (uint32_t)__cvta_generic_to_shared(sAlo);
    uint32_t bWhi = (uint32_t)__cvta_generic_to_shared(sWhi);

    float acc[8][4];
#pragma unroll
    for (int i = 0; i < 8; i++)
#pragma unroll
        for (int j = 0; j < 4; j++) acc[i][j] = 0.f;

    int lrow  = tid >> 1;
    int lhalf = (tid & 1) * 16;
    const uint32_t* aH = g_ahi + ((size_t)b * SS + mt * 64 + lrow) * 256 + lhalf;
    const uint32_t* aL = g_alo + ((size_t)b * SS + mt * 64 + lrow) * 256 + lhalf;

    for (int kc = 0; kc < 8; kc++) {
        __syncthreads();
        const uint32_t* wH = g_whi + WO_OFF + (size_t)(kc * 64 + lrow) * 256 + ntb * 32 + lhalf;
#pragma unroll
        for (int j = 0; j < 4; j++) {
            *(uint4*)&sAhi[lrow * 36 + lhalf + 4 * j] = *(const uint4*)(aH + kc * 32 + 4 * j);
            *(uint4*)&sAlo[lrow * 36 + lhalf + 4 * j] = *(const uint4*)(aL + kc * 32 + 4 * j);
            *(uint4*)&sWhi[lrow * 36 + lhalf + 4 * j] = *(const uint4*)(wH + 4 * j);
        }
        __syncthreads();
#pragma unroll
        for (int c = 0; c < 4; c++) {
            uint32_t aoff = (uint32_t)(arow * 72 + 16 * c + ad) * 2;
            uint32_t ah0, ah1, ah2, ah3, al0, al1, al2, al3;
            ldsm4(ah0, ah1, ah2, ah3, bAhi + aoff);
            ldsm4(al0, al1, al2, al3, bAlo + aoff);
#pragma unroll
            for (int ntp = 0; ntp < 4; ntp++) {
                uint32_t boff = (uint32_t)((16 * c + brow16) * 72 + 16 * ntp + 8 * jsel) * 2;
                uint32_t bh0, bh1, bh2, bh3;
                ldsm4t(bh0, bh1, bh2, bh3, bWhi + boff);
                mma_f16(acc[2 * ntp],     ah0, ah1, ah2, ah3, bh0, bh1);
                mma_f16(acc[2 * ntp],     al0, al1, al2, al3, bh0, bh1);
                mma_f16(acc[2 * ntp + 1], ah0, ah1, ah2, ah3, bh2, bh3);
                mma_f16(acc[2 * ntp + 1], al0, al1, al2, al3, bh2, bh3);
            }
        }
    }
    int r0 = mt * 64 + w * 16 + g;
    int r1 = r0 + 8;
#pragma unroll
    for (int nt = 0; nt < 8; nt++) {
        int col = ntb * 64 + nt * 8 + 2 * tig;
        if (r0 < cnt) {
            int orig = g_idx[(size_t)b * SS + r0];
            size_t off = ((size_t)b * SS + orig) * HH + col;
            float2 xv = *(const float2*)(g_xn + off);
            *(float2*)(out + off) = make_float2(acc[nt][0] + xv.x, acc[nt][1] + xv.y);
        }
        if (r1 < cnt) {
            int orig = g_idx[(size_t)b * SS + r1];
            size_t off = ((size_t)b * SS + orig) * HH + col;
            float2 xv = *(const float2*)(g_xn + off);
            *(float2*)(out + off) = make_float2(acc[nt][2] + xv.x, acc[nt][3] + xv.y);
        }
    }
}

// ---------------- launch ------------------------------------------------------
extern "C" void kernel_launch(void* const* d_in, const int* in_sizes, int n_in,
                              void* d_out, int out_size) {
    const float* x     = (const float*)d_in[0];
    const int*   mask  = (const int*)  d_in[1];
    const float* Wq    = (const float*)d_in[2];
    const float* Wk    = (const float*)d_in[3];
    const float* Wv    = (const float*)d_in[4];
    const float* Wo    = (const float*)d_in[5];
    const float* gamma = (const float*)d_in[6];
    const float* beta  = (const float*)d_in[7];
    float* out = (float*)d_out;

    cudaFuncSetAttribute(attn_kernel,
                         cudaFuncAttributeMaxDynamicSharedMemorySize, SMA_TOTAL);

    compact_kernel<<<BB, 256>>>(mask);
    ln_kernel<<<BB * SS, 128>>>(x, gamma, beta, out);
    wcvt_kernel<<<WALL / 256, 256>>>(Wq, Wk, Wv, Wo);
    qkv_mma_kernel<<<dim3(32, 96), 128>>>();
    attn_kernel<<<dim3(SS / 64, BB * NH), 128, SMA_TOTAL>>>();
    outproj_mma_kernel<<<dim3(8, BB * 32), 128>>>(out);
}

// round 15
// speedup vs baseline: 1.5469x; 1.0428x over previous
#include <cuda_runtime.h>
#include <cuda_fp16.h>
#include <math.h>
#include <stdint.h>

#define BB 4
#define SS 2048
#define HH 512
#define NH 8
#define DKK 64

// ---------------- fp16 split + mma.sync helpers (baseline PTX) ---------------
__device__ __forceinline__ uint32_t pack_h(float e0, float e1) {
    __half2 hh = __floats2half2_rn(e0, e1);
    return *(uint32_t*)&hh;
}
__device__ __forceinline__ void pack_hl(float e0, float e1, uint32_t& h, uint32_t& l) {
    __half2 hh = __floats2half2_rn(e0, e1);
    h = *(uint32_t*)&hh;
    float a = __half2float(__low2half(hh));
    float b = __half2float(__high2half(hh));
    __half2 ll = __floats2half2_rn(e0 - a, e1 - b);
    l = *(uint32_t*)&ll;
}
__device__ __forceinline__ void ldsm4(uint32_t& r0, uint32_t& r1, uint32_t& r2, uint32_t& r3,
                                      uint32_t a) {
    asm volatile("ldmatrix.sync.aligned.m8n8.x4.shared.b16 {%0,%1,%2,%3}, [%4];"
                 : "=r"(r0), "=r"(r1), "=r"(r2), "=r"(r3) : "r"(a));
}
__device__ __forceinline__ void ldsm2(uint32_t& r0, uint32_t& r1, uint32_t a) {
    asm volatile("ldmatrix.sync.aligned.m8n8.x2.shared.b16 {%0,%1}, [%2];"
                 : "=r"(r0), "=r"(r1) : "r"(a));
}
__device__ __forceinline__ void ldsm2t(uint32_t& r0, uint32_t& r1, uint32_t a) {
    asm volatile("ldmatrix.sync.aligned.m8n8.x2.trans.shared.b16 {%0,%1}, [%2];"
                 : "=r"(r0), "=r"(r1) : "r"(a));
}
__device__ __forceinline__ void ldsm4t(uint32_t& r0, uint32_t& r1, uint32_t& r2, uint32_t& r3,
                                       uint32_t a) {
    asm volatile("ldmatrix.sync.aligned.m8n8.x4.trans.shared.b16 {%0,%1,%2,%3}, [%4];"
                 : "=r"(r0), "=r"(r1), "=r"(r2), "=r"(r3) : "r"(a));
}
__device__ __forceinline__ void mma_f16(float* c, uint32_t a0, uint32_t a1,
                                        uint32_t a2, uint32_t a3,
                                        uint32_t b0, uint32_t b1) {
    asm volatile(
        "mma.sync.aligned.m16n8k16.row.col.f32.f16.f16.f32 "
        "{%0,%1,%2,%3}, {%4,%5,%6,%7}, {%8,%9}, {%0,%1,%2,%3};"
        : "+f"(c[0]), "+f"(c[1]), "+f"(c[2]), "+f"(c[3])
        : "r"(a0), "r"(a1), "r"(a2), "r"(a3), "r"(b0), "r"(b1));
}
__device__ __forceinline__ void cpasync16(uint32_t smem, const void* gptr) {
    asm volatile("cp.async.cg.shared.global [%0], [%1], 16;" :: "r"(smem), "l"(gptr) : "memory");
}
__device__ __forceinline__ void cp_commit() {
    asm volatile("cp.async.commit_group;" ::: "memory");
}
__device__ __forceinline__ void cp_wait1() {
    asm volatile("cp.async.wait_group 1;" ::: "memory");
}
__device__ __forceinline__ void cp_wait0() {
    asm volatile("cp.async.wait_group 0;" ::: "memory");
}

// ---------------- scratch ----------------------------------------------------
__device__ float g_xn[BB * SS * HH];
__device__ int   g_idx[BB * SS];
__device__ int   g_rank[BB * SS];
__device__ int   g_cnt[BB];

#define WO_OFF 393216
#define WALL   524288
__device__ uint32_t g_whi[WALL];
__device__ uint32_t g_xhi[BB * SS * 256], g_xlo[BB * SS * 256];
__device__ uint32_t g_ahi[BB * SS * 256], g_alo[BB * SS * 256];
__device__ uint32_t g_qhi[BB * NH * SS * 32], g_qlo[BB * NH * SS * 32];
__device__ uint32_t g_khi[BB * NH * SS * 32];
__device__ uint32_t g_vhi[BB * NH * SS * 32];

// ---------------- 1) mask compaction + rank map -------------------------------
__global__ void compact_kernel(const int* __restrict__ mask) {
    int b = blockIdx.x;
    int t = threadIdx.x;
    int vals[8];
    int c = 0;
#pragma unroll
    for (int i = 0; i < 8; i++) {
        vals[i] = mask[(size_t)b * SS + t * 8 + i];
        c += (vals[i] != 0);
    }
    __shared__ int s[256];
    s[t] = c;
    __syncthreads();
    for (int off = 1; off < 256; off <<= 1) {
        int v = (t >= off) ? s[t - off] : 0;
        __syncthreads();
        s[t] += v;
        __syncthreads();
    }
    int pos = s[t] - c;
#pragma unroll
    for (int i = 0; i < 8; i++) {
        int orig = t * 8 + i;
        if (vals[i]) {
            g_idx[(size_t)b * SS + pos] = orig;
            g_rank[(size_t)b * SS + orig] = pos;
            pos++;
        } else {
            g_rank[(size_t)b * SS + orig] = -1;
        }
    }
    if (t == 255) g_cnt[b] = s[255];
}

// ---------------- 2) LayerNorm fused with convert + zeroing -------------------
__global__ void ln_kernel(const float* __restrict__ x,
                          const float* __restrict__ gamma,
                          const float* __restrict__ beta,
                          float* __restrict__ out) {
    int row = blockIdx.x;
    int t = threadIdx.x;
    const float* xr = x + (size_t)row * HH;
    float4 v = *(const float4*)(xr + t * 4);
    float s  = (v.x + v.y) + (v.z + v.w);
    float sq = (v.x * v.x + v.y * v.y) + (v.z * v.z + v.w * v.w);
    __shared__ float ssum[4], ssq[4];
    for (int o = 16; o > 0; o >>= 1) {
        s  += __shfl_xor_sync(0xffffffffu, s,  o);
        sq += __shfl_xor_sync(0xffffffffu, sq, o);
    }
    if ((t & 31) == 0) { ssum[t >> 5] = s; ssq[t >> 5] = sq; }
    __syncthreads();
    float tot  = (ssum[0] + ssum[1]) + (ssum[2] + ssum[3]);
    float totq = (ssq[0]  + ssq[1])  + (ssq[2]  + ssq[3]);
    float mu  = tot * (1.0f / HH);
    float var = totq * (1.0f / HH) - mu * mu;
    float inv = rsqrtf(var + 1e-5f);

    float4 gm = *(const float4*)(gamma + t * 4);
    float4 bt = *(const float4*)(beta  + t * 4);
    float y0 = (v.x - mu) * inv * gm.x + bt.x;
    float y1 = (v.y - mu) * inv * gm.y + bt.y;
    float y2 = (v.z - mu) * inv * gm.z + bt.z;
    float y3 = (v.w - mu) * inv * gm.w + bt.w;

    int rank = g_rank[row];
    if (rank >= 0) {
        *(float4*)(g_xn + (size_t)row * HH + t * 4) = make_float4(y0, y1, y2, y3);
        uint32_t h0, l0, h1, l1;
        pack_hl(y0, y1, h0, l0);
        pack_hl(y2, y3, h1, l1);
        int b = row >> 11;
        size_t o = ((size_t)(b * SS + rank)) * 256 + t * 2;
        g_xhi[o] = h0; g_xhi[o + 1] = h1;
        g_xlo[o] = l0; g_xlo[o + 1] = l1;
    } else {
        *(float4*)(out + (size_t)row * HH + t * 4) = make_float4(0.f, 0.f, 0.f, 0.f);
    }
}

// ---------------- 3) weight convert (hi only) ----------------------------------
__global__ void wcvt_kernel(const float* __restrict__ Wq, const float* __restrict__ Wk,
                            const float* __restrict__ Wv, const float* __restrict__ Wo) {
    int i = blockIdx.x * 256 + threadIdx.x;
    const float* src;
    int rem;
    if (i < WO_OFF) {
        int which = i / 131072;
        rem = i - which * 131072;
        src = (which == 0 ? Wq : (which == 1 ? Wk : Wv));
    } else {
        rem = i - WO_OFF;
        src = Wo;
    }
    float2 v = *(const float2*)(src + (size_t)rem * 2);
    g_whi[i] = pack_h(v.x, v.y);
}

// ---------------- 4) QKV projection: fp16 2-term + cp.async double-buffer ------
#define QD_AHI 0
#define QD_ALO 9216
#define QD_WHI 18432
#define QD_STAGE 27648
#define QD_TOTAL (2 * QD_STAGE)

__global__ __launch_bounds__(128)
void qkv_mma_kernel() {
    extern __shared__ __align__(16) char smq[];
    int mt    = blockIdx.x;
    int which = blockIdx.y >> 5;
    int bn    = blockIdx.y & 31;
    int b = bn >> 3, n = bn & 7;
    int cnt = g_cnt[b];
    if (mt * 64 >= cnt) return;

    const uint32_t* Wh = g_whi + which * 131072 + n * 16384;
    uint32_t* Ch = (which == 0 ? g_qhi : (which == 1 ? g_khi : g_vhi)) + (size_t)bn * SS * 32;
    uint32_t* Cl = (which == 0) ? (g_qlo + (size_t)bn * SS * 32) : nullptr;

    uint32_t sb = (uint32_t)__cvta_generic_to_shared(smq);
    int tid  = threadIdx.x;
    int w    = tid >> 5;
    int lane = tid & 31;
    int g    = lane >> 2;
    int tig  = lane & 3;
    int laneq = lane & 15;
    int jsel  = lane >> 4;
    int arow = w * 16 + (lane & 7) + ((lane >> 3) & 1) * 8;
    int ad   = jsel * 8;
    int brow16 = (laneq & 7) + ((laneq >> 3) & 1) * 8;

    float acc[8][4];
#pragma unroll
    for (int i = 0; i < 8; i++)
#pragma unroll
        for (int j = 0; j < 4; j++) acc[i][j] = 0.f;

    int lrow  = tid >> 1;
    int lhalf = (tid & 1) * 16;
    const uint32_t* aH = g_xhi + ((size_t)b * SS + mt * 64 + lrow) * 256 + lhalf;
    const uint32_t* aL = g_xlo + ((size_t)b * SS + mt * 64 + lrow) * 256 + lhalf;
    uint32_t so_base = (uint32_t)(lrow * 36 + lhalf) * 4;

    // prologue: stage chunk 0
    {
        const uint32_t* wH = Wh + (size_t)lrow * 32 + lhalf;
#pragma unroll
        for (int j = 0; j < 4; j++) {
            uint32_t so = so_base + 16 * j;
            cpasync16(sb + QD_AHI + so, aH + 4 * j);
            cpasync16(sb + QD_ALO + so, aL + 4 * j);
            cpasync16(sb + QD_WHI + so, wH + 4 * j);
        }
        cp_commit();
    }

    for (int kc = 0; kc < 8; kc++) {
        if (kc < 7) {
            uint32_t st = sb + ((kc + 1) & 1) * QD_STAGE;
            const uint32_t* wH = Wh + (size_t)((kc + 1) * 64 + lrow) * 32 + lhalf;
#pragma unroll
            for (int j = 0; j < 4; j++) {
                uint32_t so = so_base + 16 * j;
                cpasync16(st + QD_AHI + so, aH + (kc + 1) * 32 + 4 * j);
                cpasync16(st + QD_ALO + so, aL + (kc + 1) * 32 + 4 * j);
                cpasync16(st + QD_WHI + so, wH + 4 * j);
            }
            cp_commit();
            cp_wait1();
        } else {
            cp_wait0();
        }
        __syncthreads();
        uint32_t cbase = sb + (kc & 1) * QD_STAGE;
#pragma unroll
        for (int c = 0; c < 4; c++) {
            uint32_t aoff = (uint32_t)(arow * 72 + 16 * c + ad) * 2;
            uint32_t ah0, ah1, ah2, ah3, al0, al1, al2, al3;
            ldsm4(ah0, ah1, ah2, ah3, cbase + QD_AHI + aoff);
            ldsm4(al0, al1, al2, al3, cbase + QD_ALO + aoff);
#pragma unroll
            for (int ntp = 0; ntp < 4; ntp++) {
                uint32_t boff = (uint32_t)((16 * c + brow16) * 72 + 16 * ntp + 8 * jsel) * 2;
                uint32_t bh0, bh1, bh2, bh3;
                ldsm4t(bh0, bh1, bh2, bh3, cbase + QD_WHI + boff);
                mma_f16(acc[2 * ntp],     ah0, ah1, ah2, ah3, bh0, bh1);
                mma_f16(acc[2 * ntp],     al0, al1, al2, al3, bh0, bh1);
                mma_f16(acc[2 * ntp + 1], ah0, ah1, ah2, ah3, bh2, bh3);
                mma_f16(acc[2 * ntp + 1], al0, al1, al2, al3, bh2, bh3);
            }
        }
        __syncthreads();
    }
    int r0 = mt * 64 + w * 16 + g;
    int r1 = r0 + 8;
#pragma unroll
    for (int nt = 0; nt < 8; nt++) {
        int ci = nt * 4 + tig;
        if (r0 < cnt) {
            if (which == 0) {
                uint32_t h, l;
                pack_hl(acc[nt][0], acc[nt][1], h, l);
                Ch[(size_t)r0 * 32 + ci] = h;
                Cl[(size_t)r0 * 32 + ci] = l;
            } else {
                Ch[(size_t)r0 * 32 + ci] = pack_h(acc[nt][0], acc[nt][1]);
            }
        }
        if (r1 < cnt) {
            if (which == 0) {
                uint32_t h, l;
                pack_hl(acc[nt][2], acc[nt][3], h, l);
                Ch[(size_t)r1 * 32 + ci] = h;
                Cl[(size_t)r1 * 32 + ci] = l;
            } else {
                Ch[(size_t)r1 * 32 + ci] = pack_h(acc[nt][2], acc[nt][3]);
            }
        }
    }
}

// ---------------- 5) attention: fp16 2-term + cp.async K/V double-buffer -------
#define APAD 72
#define OFF_QHI 0
#define OFF_QLO 9216
#define AT_STAGE0 18432
#define AT_STAGE 18432
#define AT_VOFF 9216
#define SMA_TOTAL (18432 + 2 * 18432)

__global__ __launch_bounds__(128)
void attn_kernel() {
    extern __shared__ __align__(16) char sm[];
    int bn = blockIdx.y;
    int b  = bn >> 3;
    int n  = bn & 7;
    int cnt = g_cnt[b];
    int qbase = blockIdx.x * 64;
    if (qbase >= cnt) return;

    int tid  = threadIdx.x;
    int w    = tid >> 5;
    int lane = tid & 31;
    int g    = lane >> 2;
    int tig  = lane & 3;
    uint32_t sb = (uint32_t)__cvta_generic_to_shared(sm);

    int lrow  = tid >> 1;
    int lhalf = tid & 1;
    uint32_t kvoff = (uint32_t)lrow * 144 + lhalf * 64;

    // Q tile (regular stores, loaded once)
    {
        const uint4* qh = (const uint4*)(g_qhi + ((size_t)bn * SS + qbase + lrow) * 32 + lhalf * 16);
        const uint4* ql = (const uint4*)(g_qlo + ((size_t)bn * SS + qbase + lrow) * 32 + lhalf * 16);
#pragma unroll
        for (int j = 0; j < 4; j++) {
            *(uint4*)(sm + OFF_QHI + kvoff + j * 16) = qh[j];
            *(uint4*)(sm + OFF_QLO + kvoff + j * 16) = ql[j];
        }
    }

    float o[8][4];
#pragma unroll
    for (int i = 0; i < 8; i++)
#pragma unroll
        for (int j = 0; j < 4; j++) o[i][j] = 0.f;
    float l0 = 0.f, l1 = 0.f;

    int q0 = w * 16;
    int arow_q = q0 + (lane & 7) + ((lane >> 3) & 1) * 8;
    int ad_sel = (lane >> 4) * 8;
    int brow   = lane & 7;
    int bsel   = ((lane >> 3) & 1) * 8;

    int ktiles = (cnt + 63) >> 6;
    // prologue: stage tile 0
    {
        size_t gsrc = ((size_t)bn * SS + lrow) * 32 + lhalf * 16;
#pragma unroll
        for (int j = 0; j < 4; j++) {
            cpasync16(sb + AT_STAGE0 + kvoff + j * 16, g_khi + gsrc + 4 * j);
            cpasync16(sb + AT_STAGE0 + AT_VOFF + kvoff + j * 16, g_vhi + gsrc + 4 * j);
        }
        cp_commit();
    }

    for (int kt = 0; kt < ktiles; kt++) {
        int kbase = kt * 64;
        if (kt + 1 < ktiles) {
            uint32_t st = sb + AT_STAGE0 + ((kt + 1) & 1) * AT_STAGE;
            size_t gsrc = ((size_t)bn * SS + (kt + 1) * 64 + lrow) * 32 + lhalf * 16;
#pragma unroll
            for (int j = 0; j < 4; j++) {
                cpasync16(st + kvoff + j * 16, g_khi + gsrc + 4 * j);
                cpasync16(st + AT_VOFF + kvoff + j * 16, g_vhi + gsrc + 4 * j);
            }
            cp_commit();
            cp_wait1();
        } else {
            cp_wait0();
        }
        __syncthreads();
        uint32_t stg = sb + AT_STAGE0 + (kt & 1) * AT_STAGE;

        float s[8][4];
#pragma unroll
        for (int i = 0; i < 8; i++)
#pragma unroll
            for (int j = 0; j < 4; j++) s[i][j] = 0.f;

#pragma unroll
        for (int c = 0; c < 4; c++) {
            uint32_t aoffq = (uint32_t)(arow_q * APAD + 16 * c + ad_sel) * 2;
            uint32_t ah0, ah1, ah2, ah3, al0, al1, al2, al3;
            ldsm4(ah0, ah1, ah2, ah3, sb + OFF_QHI + aoffq);
            ldsm4(al0, al1, al2, al3, sb + OFF_QLO + aoffq);
#pragma unroll
            for (int j = 0; j < 8; j++) {
                uint32_t boff = (uint32_t)((8 * j + brow) * APAD + 16 * c + bsel) * 2;
                uint32_t bh0, bh1;
                ldsm2(bh0, bh1, stg + boff);
                mma_f16(s[j], ah0, ah1, ah2, ah3, bh0, bh1);
                mma_f16(s[j], al0, al1, al2, al3, bh0, bh1);
            }
        }

#pragma unroll
        for (int j = 0; j < 8; j++) {
            int kg0 = kbase + 8 * j + 2 * tig;
#pragma unroll
            for (int r = 0; r < 4; r++) {
                int kg = kg0 + (r & 1);
                float p = (kg < cnt) ? __expf(s[j][r] * 0.125f) : 0.f;
                s[j][r] = p;
                if (r < 2) l0 += p; else l1 += p;
            }
        }

#pragma unroll
        for (int c = 0; c < 4; c++) {
            uint32_t ph0, ph1, ph2, ph3, pl0, pl1, pl2, pl3;
            pack_hl(s[2 * c][0],     s[2 * c][1],     ph0, pl0);
            pack_hl(s[2 * c][2],     s[2 * c][3],     ph1, pl1);
            pack_hl(s[2 * c + 1][0], s[2 * c + 1][1], ph2, pl2);
            pack_hl(s[2 * c + 1][2], s[2 * c + 1][3], ph3, pl3);
#pragma unroll
            for (int dt = 0; dt < 8; dt++) {
                uint32_t voff = (uint32_t)((16 * c + bsel + brow) * APAD + 8 * dt) * 2;
                uint32_t vh0, vh1;
                ldsm2t(vh0, vh1, stg + AT_VOFF + voff);
                mma_f16(o[dt], ph0, ph1, ph2, ph3, vh0, vh1);
                mma_f16(o[dt], pl0, pl1, pl2, pl3, vh0, vh1);
            }
        }
        __syncthreads();
    }

    l0 += __shfl_xor_sync(0xffffffffu, l0, 1);
    l0 += __shfl_xor_sync(0xffffffffu, l0, 2);
    l1 += __shfl_xor_sync(0xffffffffu, l1, 1);
    l1 += __shfl_xor_sync(0xffffffffu, l1, 2);
    float inv0 = 1.0f / l0;
    float inv1 = 1.0f / l1;

    int r0 = qbase + q0 + g;
    int r1 = r0 + 8;
#pragma unroll
    for (int dt = 0; dt < 8; dt++) {
        int cu = n * 32 + dt * 4 + tig;
        if (r0 < cnt) {
            uint32_t h, l;
            pack_hl(o[dt][0] * inv0, o[dt][1] * inv0, h, l);
            g_ahi[((size_t)b * SS + r0) * 256 + cu] = h;
            g_alo[((size_t)b * SS + r0) * 256 + cu] = l;
        }
        if (r1 < cnt) {
            uint32_t h, l;
            pack_hl(o[dt][2] * inv1, o[dt][3] * inv1, h, l);
            g_ahi[((size_t)b * SS + r1) * 256 + cu] = h;
            g_alo[((size_t)b * SS + r1) * 256 + cu] = l;
        }
    }
}

// ---------------- 6) out projection: fp16 2-term + cp.async --------------------
__global__ __launch_bounds__(128)
void outproj_mma_kernel(float* __restrict__ out) {
    extern __shared__ __align__(16) char smq[];
    int ntb = blockIdx.x;
    int b   = blockIdx.y >> 5;
    int mt  = blockIdx.y & 31;
    int cnt = g_cnt[b];
    if (mt * 64 >= cnt) return;

    uint32_t sb = (uint32_t)__cvta_generic_to_shared(smq);
    int tid  = threadIdx.x;
    int w    = tid >> 5;
    int lane = tid & 31;
    int g    = lane >> 2;
    int tig  = lane & 3;
    int laneq = lane & 15;
    int jsel  = lane >> 4;
    int arow = w * 16 + (lane & 7) + ((lane >> 3) & 1) * 8;
    int ad   = jsel * 8;
    int brow16 = (laneq & 7) + ((laneq >> 3) & 1) * 8;

    float acc[8][4];
#pragma unroll
    for (int i = 0; i < 8; i++)
#pragma unroll
        for (int j = 0; j < 4; j++) acc[i][j] = 0.f;

    int lrow  = tid >> 1;
    int lhalf = (tid & 1) * 16;
    const uint32_t* aH = g_ahi + ((size_t)b * SS + mt * 64 + lrow) * 256 + lhalf;
    const uint32_t* aL = g_alo + ((size_t)b * SS + mt * 64 + lrow) * 256 + lhalf;
    const uint32_t* WhBase = g_whi + WO_OFF + (size_t)lrow * 256 + ntb * 32 + lhalf;
    uint32_t so_base = (uint32_t)(lrow * 36 + lhalf) * 4;

    {
#pragma unroll
        for (int j = 0; j < 4; j++) {
            uint32_t so = so_base + 16 * j;
            cpasync16(sb + QD_AHI + so, aH + 4 * j);
            cpasync16(sb + QD_ALO + so, aL + 4 * j);
            cpasync16(sb + QD_WHI + so, WhBase + 4 * j);
        }
        cp_commit();
    }

    for (int kc = 0; kc < 8; kc++) {
        if (kc < 7) {
            uint32_t st = sb + ((kc + 1) & 1) * QD_STAGE;
            size_t woff = (size_t)(kc + 1) * 64 * 256;
#pragma unroll
            for (int j = 0; j < 4; j++) {
                uint32_t so = so_base + 16 * j;
                cpasync16(st + QD_AHI + so, aH + (kc + 1) * 32 + 4 * j);
                cpasync16(st + QD_ALO + so, aL + (kc + 1) * 32 + 4 * j);
                cpasync16(st + QD_WHI + so, WhBase + woff + 4 * j);
            }
            cp_commit();
            cp_wait1();
        } else {
            cp_wait0();
        }
        __syncthreads();
        uint32_t cbase = sb + (kc & 1) * QD_STAGE;
#pragma unroll
        for (int c = 0; c < 4; c++) {
            uint32_t aoff = (uint32_t)(arow * 72 + 16 * c + ad) * 2;
            uint32_t ah0, ah1, ah2, ah3, al0, al1, al2, al3;
            ldsm4(ah0, ah1, ah2, ah3, cbase + QD_AHI + aoff);
            ldsm4(al0, al1, al2, al3, cbase + QD_ALO + aoff);
#pragma unroll
            for (int ntp = 0; ntp < 4; ntp++) {
                uint32_t boff = (uint32_t)((16 * c + brow16) * 72 + 16 * ntp + 8 * jsel) * 2;
                uint32_t bh0, bh1, bh2, bh3;
                ldsm4t(bh0, bh1, bh2, bh3, cbase + QD_WHI + boff);
                mma_f16(acc[2 * ntp],     ah0, ah1, ah2, ah3, bh0, bh1);
                mma_f16(acc[2 * ntp],     al0, al1, al2, al3, bh0, bh1);
                mma_f16(acc[2 * ntp + 1], ah0, ah1, ah2, ah3, bh2, bh3);
                mma_f16(acc[2 * ntp + 1], al0, al1, al2, al3, bh2, bh3);
            }
        }
        __syncthreads();
    }
    int r0 = mt * 64 + w * 16 + g;
    int r1 = r0 + 8;
#pragma unroll
    for (int nt = 0; nt < 8; nt++) {
        int col = ntb * 64 + nt * 8 + 2 * tig;
        if (r0 < cnt) {
            int orig = g_idx[(size_t)b * SS + r0];
            size_t off = ((size_t)b * SS + orig) * HH + col;
            float2 xv = *(const float2*)(g_xn + off);
            *(float2*)(out + off) = make_float2(acc[nt][0] + xv.x, acc[nt][1] + xv.y);
        }
        if (r1 < cnt) {
            int orig = g_idx[(size_t)b * SS + r1];
            size_t off = ((size_t)b * SS + orig) * HH + col;
            float2 xv = *(const float2*)(g_xn + off);
            *(float2*)(out + off) = make_float2(acc[nt][2] + xv.x, acc[nt][3] + xv.y);
        }
    }
}

// ---------------- launch ------------------------------------------------------
extern "C" void kernel_launch(void* const* d_in, const int* in_sizes, int n_in,
                              void* d_out, int out_size) {
    const float* x     = (const float*)d_in[0];
    const int*   mask  = (const int*)  d_in[1];
    const float* Wq    = (const float*)d_in[2];
    const float* Wk    = (const float*)d_in[3];
    const float* Wv    = (const float*)d_in[4];
    const float* Wo    = (const float*)d_in[5];
    const float* gamma = (const float*)d_in[6];
    const float* beta  = (const float*)d_in[7];
    float* out = (float*)d_out;

    cudaFuncSetAttribute(attn_kernel,
                         cudaFuncAttributeMaxDynamicSharedMemorySize, SMA_TOTAL);
    cudaFuncSetAttribute(qkv_mma_kernel,
                         cudaFuncAttributeMaxDynamicSharedMemorySize, QD_TOTAL);
    cudaFuncSetAttribute(outproj_mma_kernel,
                         cudaFuncAttributeMaxDynamicSharedMemorySize, QD_TOTAL);

    compact_kernel<<<BB, 256>>>(mask);
    ln_kernel<<<BB * SS, 128>>>(x, gamma, beta, out);
    wcvt_kernel<<<WALL / 256, 256>>>(Wq, Wk, Wv, Wo);
    qkv_mma_kernel<<<dim3(32, 96), 128, QD_TOTAL>>>();
    attn_kernel<<<dim3(SS / 64, BB * NH), 128, SMA_TOTAL>>>();
    outproj_mma_kernel<<<dim3(8, BB * 32), 128, QD_TOTAL>>>(out);
}

// round 16
// speedup vs baseline: 2.1553x; 1.3933x over previous
#include <cuda_runtime.h>
#include <cuda_fp16.h>
#include <math.h>
#include <stdint.h>

#define BB 4
#define SS 2048
#define HH 512
#define NH 8
#define DKK 64

// ---------------- fp16 + mma.sync helpers (baseline PTX) ---------------------
__device__ __forceinline__ uint32_t pack_h(float e0, float e1) {
    __half2 hh = __floats2half2_rn(e0, e1);
    return *(uint32_t*)&hh;
}
__device__ __forceinline__ void ldsm4(uint32_t& r0, uint32_t& r1, uint32_t& r2, uint32_t& r3,
                                      uint32_t a) {
    asm volatile("ldmatrix.sync.aligned.m8n8.x4.shared.b16 {%0,%1,%2,%3}, [%4];"
                 : "=r"(r0), "=r"(r1), "=r"(r2), "=r"(r3) : "r"(a));
}
__device__ __forceinline__ void ldsm2(uint32_t& r0, uint32_t& r1, uint32_t a) {
    asm volatile("ldmatrix.sync.aligned.m8n8.x2.shared.b16 {%0,%1}, [%2];"
                 : "=r"(r0), "=r"(r1) : "r"(a));
}
__device__ __forceinline__ void ldsm2t(uint32_t& r0, uint32_t& r1, uint32_t a) {
    asm volatile("ldmatrix.sync.aligned.m8n8.x2.trans.shared.b16 {%0,%1}, [%2];"
                 : "=r"(r0), "=r"(r1) : "r"(a));
}
__device__ __forceinline__ void ldsm4t(uint32_t& r0, uint32_t& r1, uint32_t& r2, uint32_t& r3,
                                       uint32_t a) {
    asm volatile("ldmatrix.sync.aligned.m8n8.x4.trans.shared.b16 {%0,%1,%2,%3}, [%4];"
                 : "=r"(r0), "=r"(r1), "=r"(r2), "=r"(r3) : "r"(a));
}
__device__ __forceinline__ void mma_f16(float* c, uint32_t a0, uint32_t a1,
                                        uint32_t a2, uint32_t a3,
                                        uint32_t b0, uint32_t b1) {
    asm volatile(
        "mma.sync.aligned.m16n8k16.row.col.f32.f16.f16.f32 "
        "{%0,%1,%2,%3}, {%4,%5,%6,%7}, {%8,%9}, {%0,%1,%2,%3};"
        : "+f"(c[0]), "+f"(c[1]), "+f"(c[2]), "+f"(c[3])
        : "r"(a0), "r"(a1), "r"(a2), "r"(a3), "r"(b0), "r"(b1));
}
__device__ __forceinline__ void cpasync16(uint32_t smem, const void* gptr) {
    asm volatile("cp.async.cg.shared.global [%0], [%1], 16;" :: "r"(smem), "l"(gptr) : "memory");
}
__device__ __forceinline__ void cp_commit() {
    asm volatile("cp.async.commit_group;" ::: "memory");
}
__device__ __forceinline__ void cp_wait1() {
    asm volatile("cp.async.wait_group 1;" ::: "memory");
}
__device__ __forceinline__ void cp_wait0() {
    asm volatile("cp.async.wait_group 0;" ::: "memory");
}

// ---------------- scratch ----------------------------------------------------
__device__ float g_xn[BB * SS * HH];
__device__ int   g_idx[BB * SS];
__device__ int   g_rank[BB * SS];
__device__ int   g_cnt[BB];

#define WO_OFF 393216
#define WALL   524288
__device__ uint32_t g_whi[WALL];
__device__ uint32_t g_xhi[BB * SS * 256];
__device__ uint32_t g_ahi[BB * SS * 256];
__device__ uint32_t g_qhi[BB * NH * SS * 32];
__device__ uint32_t g_khi[BB * NH * SS * 32];
__device__ uint32_t g_vhi[BB * NH * SS * 32];

// ---------------- 1) mask compaction + rank map -------------------------------
__global__ void compact_kernel(const int* __restrict__ mask) {
    int b = blockIdx.x;
    int t = threadIdx.x;
    int vals[8];
    int c = 0;
#pragma unroll
    for (int i = 0; i < 8; i++) {
        vals[i] = mask[(size_t)b * SS + t * 8 + i];
        c += (vals[i] != 0);
    }
    __shared__ int s[256];
    s[t] = c;
    __syncthreads();
    for (int off = 1; off < 256; off <<= 1) {
        int v = (t >= off) ? s[t - off] : 0;
        __syncthreads();
        s[t] += v;
        __syncthreads();
    }
    int pos = s[t] - c;
#pragma unroll
    for (int i = 0; i < 8; i++) {
        int orig = t * 8 + i;
        if (vals[i]) {
            g_idx[(size_t)b * SS + pos] = orig;
            g_rank[(size_t)b * SS + orig] = pos;
            pos++;
        } else {
            g_rank[(size_t)b * SS + orig] = -1;
        }
    }
    if (t == 255) g_cnt[b] = s[255];
}

// ---------------- 2) LayerNorm fused with convert + zeroing -------------------
__global__ void ln_kernel(const float* __restrict__ x,
                          const float* __restrict__ gamma,
                          const float* __restrict__ beta,
                          float* __restrict__ out) {
    int row = blockIdx.x;
    int t = threadIdx.x;
    const float* xr = x + (size_t)row * HH;
    float4 v = *(const float4*)(xr + t * 4);
    float s  = (v.x + v.y) + (v.z + v.w);
    float sq = (v.x * v.x + v.y * v.y) + (v.z * v.z + v.w * v.w);
    __shared__ float ssum[4], ssq[4];
    for (int o = 16; o > 0; o >>= 1) {
        s  += __shfl_xor_sync(0xffffffffu, s,  o);
        sq += __shfl_xor_sync(0xffffffffu, sq, o);
    }
    if ((t & 31) == 0) { ssum[t >> 5] = s; ssq[t >> 5] = sq; }
    __syncthreads();
    float tot  = (ssum[0] + ssum[1]) + (ssum[2] + ssum[3]);
    float totq = (ssq[0]  + ssq[1])  + (ssq[2]  + ssq[3]);
    float mu  = tot * (1.0f / HH);
    float var = totq * (1.0f / HH) - mu * mu;
    float inv = rsqrtf(var + 1e-5f);

    float4 gm = *(const float4*)(gamma + t * 4);
    float4 bt = *(const float4*)(beta  + t * 4);
    float y0 = (v.x - mu) * inv * gm.x + bt.x;
    float y1 = (v.y - mu) * inv * gm.y + bt.y;
    float y2 = (v.z - mu) * inv * gm.z + bt.z;
    float y3 = (v.w - mu) * inv * gm.w + bt.w;

    int rank = g_rank[row];
    if (rank >= 0) {
        *(float4*)(g_xn + (size_t)row * HH + t * 4) = make_float4(y0, y1, y2, y3);
        int b = row >> 11;
        size_t o = ((size_t)(b * SS + rank)) * 256 + t * 2;
        g_xhi[o]     = pack_h(y0, y1);
        g_xhi[o + 1] = pack_h(y2, y3);
    } else {
        *(float4*)(out + (size_t)row * HH + t * 4) = make_float4(0.f, 0.f, 0.f, 0.f);
    }
}

// ---------------- 3) weight convert --------------------------------------------
__global__ void wcvt_kernel(const float* __restrict__ Wq, const float* __restrict__ Wk,
                            const float* __restrict__ Wv, const float* __restrict__ Wo) {
    int i = blockIdx.x * 256 + threadIdx.x;
    const float* src;
    int rem;
    if (i < WO_OFF) {
        int which = i / 131072;
        rem = i - which * 131072;
        src = (which == 0 ? Wq : (which == 1 ? Wk : Wv));
    } else {
        rem = i - WO_OFF;
        src = Wo;
    }
    float2 v = *(const float2*)(src + (size_t)rem * 2);
    g_whi[i] = pack_h(v.x, v.y);
}

// ---------------- 4) QKV projection: pure fp16 + cp.async ----------------------
#define QD_AHI 0
#define QD_WHI 9216
#define QD_STAGE 18432
#define QD_TOTAL (2 * QD_STAGE)

__global__ __launch_bounds__(128)
void qkv_mma_kernel() {
    extern __shared__ __align__(16) char smq[];
    int mt    = blockIdx.x;
    int which = blockIdx.y >> 5;
    int bn    = blockIdx.y & 31;
    int b = bn >> 3, n = bn & 7;
    int cnt = g_cnt[b];
    if (mt * 64 >= cnt) return;

    const uint32_t* Wh = g_whi + which * 131072 + n * 16384;
    uint32_t* Ch = (which == 0 ? g_qhi : (which == 1 ? g_khi : g_vhi)) + (size_t)bn * SS * 32;

    uint32_t sb = (uint32_t)__cvta_generic_to_shared(smq);
    int tid  = threadIdx.x;
    int w    = tid >> 5;
    int lane = tid & 31;
    int g    = lane >> 2;
    int tig  = lane & 3;
    int laneq = lane & 15;
    int jsel  = lane >> 4;
    int arow = w * 16 + (lane & 7) + ((lane >> 3) & 1) * 8;
    int ad   = jsel * 8;
    int brow16 = (laneq & 7) + ((laneq >> 3) & 1) * 8;

    float acc[8][4];
#pragma unroll
    for (int i = 0; i < 8; i++)
#pragma unroll
        for (int j = 0; j < 4; j++) acc[i][j] = 0.f;

    int lrow  = tid >> 1;
    int lhalf = (tid & 1) * 16;
    const uint32_t* aH = g_xhi + ((size_t)b * SS + mt * 64 + lrow) * 256 + lhalf;
    uint32_t so_base = (uint32_t)(lrow * 36 + lhalf) * 4;

    {
        const uint32_t* wH = Wh + (size_t)lrow * 32 + lhalf;
#pragma unroll
        for (int j = 0; j < 4; j++) {
            uint32_t so = so_base + 16 * j;
            cpasync16(sb + QD_AHI + so, aH + 4 * j);
            cpasync16(sb + QD_WHI + so, wH + 4 * j);
        }
        cp_commit();
    }

    for (int kc = 0; kc < 8; kc++) {
        if (kc < 7) {
            uint32_t st = sb + ((kc + 1) & 1) * QD_STAGE;
            const uint32_t* wH = Wh + (size_t)((kc + 1) * 64 + lrow) * 32 + lhalf;
#pragma unroll
            for (int j = 0; j < 4; j++) {
                uint32_t so = so_base + 16 * j;
                cpasync16(st + QD_AHI + so, aH + (kc + 1) * 32 + 4 * j);
                cpasync16(st + QD_WHI + so, wH + 4 * j);
            }
            cp_commit();
            cp_wait1();
        } else {
            cp_wait0();
        }
        __syncthreads();
        uint32_t cbase = sb + (kc & 1) * QD_STAGE;
#pragma unroll
        for (int c = 0; c < 4; c++) {
            uint32_t aoff = (uint32_t)(arow * 72 + 16 * c + ad) * 2;
            uint32_t ah0, ah1, ah2, ah3;
            ldsm4(ah0, ah1, ah2, ah3, cbase + QD_AHI + aoff);
#pragma unroll
            for (int ntp = 0; ntp < 4; ntp++) {
                uint32_t boff = (uint32_t)((16 * c + brow16) * 72 + 16 * ntp + 8 * jsel) * 2;
                uint32_t bh0, bh1, bh2, bh3;
                ldsm4t(bh0, bh1, bh2, bh3, cbase + QD_WHI + boff);
                mma_f16(acc[2 * ntp],     ah0, ah1, ah2, ah3, bh0, bh1);
                mma_f16(acc[2 * ntp + 1], ah0, ah1, ah2, ah3, bh2, bh3);
            }
        }
        __syncthreads();
    }
    int r0 = mt * 64 + w * 16 + g;
    int r1 = r0 + 8;
#pragma unroll
    for (int nt = 0; nt < 8; nt++) {
        int ci = nt * 4 + tig;
        if (r0 < cnt) Ch[(size_t)r0 * 32 + ci] = pack_h(acc[nt][0], acc[nt][1]);
        if (r1 < cnt) Ch[(size_t)r1 * 32 + ci] = pack_h(acc[nt][2], acc[nt][3]);
    }
}

// ---------------- 5) attention: pure fp16 + cp.async K/V double-buffer ---------
#define APAD 72
#define OFF_QHI 0
#define AT_STAGE0 9216
#define AT_STAGE 18432
#define AT_VOFF 9216
#define SMA_TOTAL (9216 + 2 * 18432)

__global__ __launch_bounds__(128)
void attn_kernel() {
    extern __shared__ __align__(16) char sm[];
    int bn = blockIdx.y;
    int b  = bn >> 3;
    int n  = bn & 7;
    int cnt = g_cnt[b];
    int qbase = blockIdx.x * 64;
    if (qbase >= cnt) return;

    int tid  = threadIdx.x;
    int w    = tid >> 5;
    int lane = tid & 31;
    int g    = lane >> 2;
    int tig  = lane & 3;
    uint32_t sb = (uint32_t)__cvta_generic_to_shared(sm);

    int lrow  = tid >> 1;
    int lhalf = tid & 1;
    uint32_t kvoff = (uint32_t)lrow * 144 + lhalf * 64;

    {
        const uint4* qh = (const uint4*)(g_qhi + ((size_t)bn * SS + qbase + lrow) * 32 + lhalf * 16);
#pragma unroll
        for (int j = 0; j < 4; j++)
            *(uint4*)(sm + OFF_QHI + kvoff + j * 16) = qh[j];
    }

    float o[8][4];
#pragma unroll
    for (int i = 0; i < 8; i++)
#pragma unroll
        for (int j = 0; j < 4; j++) o[i][j] = 0.f;
    float l0 = 0.f, l1 = 0.f;

    int q0 = w * 16;
    int arow_q = q0 + (lane & 7) + ((lane >> 3) & 1) * 8;
    int ad_sel = (lane >> 4) * 8;
    int brow   = lane & 7;
    int bsel   = ((lane >> 3) & 1) * 8;

    int ktiles = (cnt + 63) >> 6;
    {
        size_t gsrc = ((size_t)bn * SS + lrow) * 32 + lhalf * 16;
#pragma unroll
        for (int j = 0; j < 4; j++) {
            cpasync16(sb + AT_STAGE0 + kvoff + j * 16, g_khi + gsrc + 4 * j);
            cpasync16(sb + AT_STAGE0 + AT_VOFF + kvoff + j * 16, g_vhi + gsrc + 4 * j);
        }
        cp_commit();
    }

    for (int kt = 0; kt < ktiles; kt++) {
        int kbase = kt * 64;
        if (kt + 1 < ktiles) {
            uint32_t st = sb + AT_STAGE0 + ((kt + 1) & 1) * AT_STAGE;
            size_t gsrc = ((size_t)bn * SS + (kt + 1) * 64 + lrow) * 32 + lhalf * 16;
#pragma unroll
            for (int j = 0; j < 4; j++) {
                cpasync16(st + kvoff + j * 16, g_khi + gsrc + 4 * j);
                cpasync16(st + AT_VOFF + kvoff + j * 16, g_vhi + gsrc + 4 * j);
            }
            cp_commit();
            cp_wait1();
        } else {
            cp_wait0();
        }
        __syncthreads();
        uint32_t stg = sb + AT_STAGE0 + (kt & 1) * AT_STAGE;

        float s[8][4];
#pragma unroll
        for (int i = 0; i < 8; i++)
#pragma unroll
            for (int j = 0; j < 4; j++) s[i][j] = 0.f;

#pragma unroll
        for (int c = 0; c < 4; c++) {
            uint32_t aoffq = (uint32_t)(arow_q * APAD + 16 * c + ad_sel) * 2;
            uint32_t ah0, ah1, ah2, ah3;
            ldsm4(ah0, ah1, ah2, ah3, sb + OFF_QHI + aoffq);
#pragma unroll
            for (int j = 0; j < 8; j++) {
                uint32_t boff = (uint32_t)((8 * j + brow) * APAD + 16 * c + bsel) * 2;
                uint32_t bh0, bh1;
                ldsm2(bh0, bh1, stg + boff);
                mma_f16(s[j], ah0, ah1, ah2, ah3, bh0, bh1);
            }
        }

#pragma unroll
        for (int j = 0; j < 8; j++) {
            int kg0 = kbase + 8 * j + 2 * tig;
#pragma unroll
            for (int r = 0; r < 4; r++) {
                int kg = kg0 + (r & 1);
                float p = (kg < cnt) ? __expf(s[j][r] * 0.125f) : 0.f;
                s[j][r] = p;
                if (r < 2) l0 += p; else l1 += p;
            }
        }

#pragma unroll
        for (int c = 0; c < 4; c++) {
            uint32_t ph0 = pack_h(s[2 * c][0],     s[2 * c][1]);
            uint32_t ph1 = pack_h(s[2 * c][2],     s[2 * c][3]);
            uint32_t ph2 = pack_h(s[2 * c + 1][0], s[2 * c + 1][1]);
            uint32_t ph3 = pack_h(s[2 * c + 1][2], s[2 * c + 1][3]);
#pragma unroll
            for (int dt = 0; dt < 8; dt++) {
                uint32_t voff = (uint32_t)((16 * c + bsel + brow) * APAD + 8 * dt) * 2;
                uint32_t vh0, vh1;
                ldsm2t(vh0, vh1, stg + AT_VOFF + voff);
                mma_f16(o[dt], ph0, ph1, ph2, ph3, vh0, vh1);
            }
        }
        __syncthreads();
    }

    l0 += __shfl_xor_sync(0xffffffffu, l0, 1);
    l0 += __shfl_xor_sync(0xffffffffu, l0, 2);
    l1 += __shfl_xor_sync(0xffffffffu, l1, 1);
    l1 += __shfl_xor_sync(0xffffffffu, l1, 2);
    float inv0 = 1.0f / l0;
    float inv1 = 1.0f / l1;

    int r0 = qbase + q0 + g;
    int r1 = r0 + 8;
#pragma unroll
    for (int dt = 0; dt < 8; dt++) {
        int cu = n * 32 + dt * 4 + tig;
        if (r0 < cnt)
            g_ahi[((size_t)b * SS + r0) * 256 + cu] = pack_h(o[dt][0] * inv0, o[dt][1] * inv0);
        if (r1 < cnt)
            g_ahi[((size_t)b * SS + r1) * 256 + cu] = pack_h(o[dt][2] * inv1, o[dt][3] * inv1);
    }
}

// ---------------- 6) out projection: pure fp16 + cp.async ----------------------
__global__ __launch_bounds__(128)
void outproj_mma_kernel(float* __restrict__ out) {
    extern __shared__ __align__(16) char smq[];
    int ntb = blockIdx.x;
    int b   = blockIdx.y >> 5;
    int mt  = blockIdx.y & 31;
    int cnt = g_cnt[b];
    if (mt * 64 >= cnt) return;

    uint32_t sb = (uint32_t)__cvta_generic_to_shared(smq);
    int tid  = threadIdx.x;
    int w    = tid >> 5;
    int lane = tid & 31;
    int g    = lane >> 2;
    int tig  = lane & 3;
    int laneq = lane & 15;
    int jsel  = lane >> 4;
    int arow = w * 16 + (lane & 7) + ((lane >> 3) & 1) * 8;
    int ad   = jsel * 8;
    int brow16 = (laneq & 7) + ((laneq >> 3) & 1) * 8;

    float acc[8][4];
#pragma unroll
    for (int i = 0; i < 8; i++)
#pragma unroll
        for (int j = 0; j < 4; j++) acc[i][j] = 0.f;

    int lrow  = tid >> 1;
    int lhalf = (tid & 1) * 16;
    const uint32_t* aH = g_ahi + ((size_t)b * SS + mt * 64 + lrow) * 256 + lhalf;
    const uint32_t* WhBase = g_whi + WO_OFF + (size_t)lrow * 256 + ntb * 32 + lhalf;
    uint32_t so_base = (uint32_t)(lrow * 36 + lhalf) * 4;

    {
#pragma unroll
        for (int j = 0; j < 4; j++) {
            uint32_t so = so_base + 16 * j;
            cpasync16(sb + QD_AHI + so, aH + 4 * j);
            cpasync16(sb + QD_WHI + so, WhBase + 4 * j);
        }
        cp_commit();
    }

    for (int kc = 0; kc < 8; kc++) {
        if (kc < 7) {
            uint32_t st = sb + ((kc + 1) & 1) * QD_STAGE;
            size_t woff = (size_t)(kc + 1) * 64 * 256;
#pragma unroll
            for (int j = 0; j < 4; j++) {
                uint32_t so = so_base + 16 * j;
                cpasync16(st + QD_AHI + so, aH + (kc + 1) * 32 + 4 * j);
                cpasync16(st + QD_WHI + so, WhBase + woff + 4 * j);
            }
            cp_commit();
            cp_wait1();
        } else {
            cp_wait0();
        }
        __syncthreads();
        uint32_t cbase = sb + (kc & 1) * QD_STAGE;
#pragma unroll
        for (int c = 0; c < 4; c++) {
            uint32_t aoff = (uint32_t)(arow * 72 + 16 * c + ad) * 2;
            uint32_t ah0, ah1, ah2, ah3;
            ldsm4(ah0, ah1, ah2, ah3, cbase + QD_AHI + aoff);
#pragma unroll
            for (int ntp = 0; ntp < 4; ntp++) {
                uint32_t boff = (uint32_t)((16 * c + brow16) * 72 + 16 * ntp + 8 * jsel) * 2;
                uint32_t bh0, bh1, bh2, bh3;
                ldsm4t(bh0, bh1, bh2, bh3, cbase + QD_WHI + boff);
                mma_f16(acc[2 * ntp],     ah0, ah1, ah2, ah3, bh0, bh1);
                mma_f16(acc[2 * ntp + 1], ah0, ah1, ah2, ah3, bh2, bh3);
            }
        }
        __syncthreads();
    }
    int r0 = mt * 64 + w * 16 + g;
    int r1 = r0 + 8;
#pragma unroll
    for (int nt = 0; nt < 8; nt++) {
        int col = ntb * 64 + nt * 8 + 2 * tig;
        if (r0 < cnt) {
            int orig = g_idx[(size_t)b * SS + r0];
            size_t off = ((size_t)b * SS + orig) * HH + col;
            float2 xv = *(const float2*)(g_xn + off);
            *(float2*)(out + off) = make_float2(acc[nt][0] + xv.x, acc[nt][1] + xv.y);
        }
        if (r1 < cnt) {
            int orig = g_idx[(size_t)b * SS + r1];
            size_t off = ((size_t)b * SS + orig) * HH + col;
            float2 xv = *(const float2*)(g_xn + off);
            *(float2*)(out + off) = make_float2(acc[nt][2] + xv.x, acc[nt][3] + xv.y);
        }
    }
}

// ---------------- launch ------------------------------------------------------
extern "C" void kernel_launch(void* const* d_in, const int* in_sizes, int n_in,
                              void* d_out, int out_size) {
    const float* x     = (const float*)d_in[0];
    const int*   mask  = (const int*)  d_in[1];
    const float* Wq    = (const float*)d_in[2];
    const float* Wk    = (const float*)d_in[3];
    const float* Wv    = (const float*)d_in[4];
    const float* Wo    = (const float*)d_in[5];
    const float* gamma = (const float*)d_in[6];
    const float* beta  = (const float*)d_in[7];
    float* out = (float*)d_out;

    cudaFuncSetAttribute(attn_kernel,
                         cudaFuncAttributeMaxDynamicSharedMemorySize, SMA_TOTAL);
    cudaFuncSetAttribute(qkv_mma_kernel,
                         cudaFuncAttributeMaxDynamicSharedMemorySize, QD_TOTAL);
    cudaFuncSetAttribute(outproj_mma_kernel,
                         cudaFuncAttributeMaxDynamicSharedMemorySize, QD_TOTAL);

    compact_kernel<<<BB, 256>>>(mask);
    ln_kernel<<<BB * SS, 128>>>(x, gamma, beta, out);
    wcvt_kernel<<<WALL / 256, 256>>>(Wq, Wk, Wv, Wo);
    qkv_mma_kernel<<<dim3(32, 96), 128, QD_TOTAL>>>();
    attn_kernel<<<dim3(SS / 64, BB * NH), 128, SMA_TOTAL>>>();
    outproj_mma_kernel<<<dim3(8, BB * 32), 128, QD_TOTAL>>>(out);
}